// round 7
// baseline (speedup 1.0000x reference)
#include <cuda_runtime.h>
#include <cuda_bf16.h>
#include <math.h>
#include <stdint.h>

// Problem constants
#define BB   16
#define CC   256
#define HW   4096     // 64*64
#define CS   32
#define NP   1024     // 32*32
#define M1   320      // CS + CS + CC
#define YM   384      // M1 padded to multiple of 128

// ---------------- device scratch ----------------
__device__ float g_W[YM * CC];                  // packed [wq;wk;wv;0], tf32-rounded
__device__ float g_bias[YM];
__device__ float g_Wo[CC * CC];                 // wo, tf32-rounded
__device__ float g_Xr[(long)BB * CC * HW];      // x, tf32-rounded (GEMM1 B operand)
__device__ float g_Y[(long)BB * YM * HW];       // QKV conv outputs (fp32, exact for energy)
__device__ float g_Q[(long)BB * CS * NP];
__device__ float g_Vp[(long)BB * CC * NP];      // pooled V * invsum, tf32-rounded
__device__ float g_P[(long)BB * NP * HW];       // exp(E), tf32-rounded
__device__ float g_invsum[(long)BB * NP];
__device__ float g_out1[(long)BB * CC * HW];    // V' @ P, tf32-rounded

// ---------------- helpers ----------------
__device__ __forceinline__ float tf32r(float f) {
    uint32_t u;
    asm("cvt.rna.tf32.f32 %0, %1;" : "=r"(u) : "f"(f));
    return __uint_as_float(u);
}

__device__ __forceinline__ void mma_tf32(float& c0, float& c1, float& c2, float& c3,
                                         uint32_t a0, uint32_t a1, uint32_t a2, uint32_t a3,
                                         uint32_t b0, uint32_t b1)
{
    asm volatile(
        "mma.sync.aligned.m16n8k8.row.col.f32.tf32.tf32.f32 "
        "{%0,%1,%2,%3}, {%4,%5,%6,%7}, {%8,%9}, {%0,%1,%2,%3};\n"
        : "+f"(c0), "+f"(c1), "+f"(c2), "+f"(c3)
        : "r"(a0), "r"(a1), "r"(a2), "r"(a3), "r"(b0), "r"(b1));
}

__device__ __forceinline__ void cp16(void* smem, const void* gmem) {
    uint32_t sa = (uint32_t)__cvta_generic_to_shared(smem);
    asm volatile("cp.async.ca.shared.global [%0], [%1], 16;\n" :: "r"(sa), "l"(gmem));
}
__device__ __forceinline__ void cp_commit() { asm volatile("cp.async.commit_group;\n"); }
template<int N>
__device__ __forceinline__ void cp_wait() { asm volatile("cp.async.wait_group %0;\n" :: "n"(N)); }

// ---------------- pack weights (tf32-rounded) ----------------
__global__ void pack_kernel(const float* __restrict__ wq, const float* __restrict__ bq,
                            const float* __restrict__ wk, const float* __restrict__ bk,
                            const float* __restrict__ wv, const float* __restrict__ bv,
                            const float* __restrict__ wo)
{
    int idx = blockIdx.x * blockDim.x + threadIdx.x;
    if (idx < YM * CC) {
        int r = idx / CC, c = idx % CC;
        float v;
        if (r < CS)           v = wq[r * CC + c];
        else if (r < 2 * CS)  v = wk[(r - CS) * CC + c];
        else if (r < M1)      v = wv[(r - 2 * CS) * CC + c];
        else                  v = 0.0f;
        g_W[idx] = tf32r(v);
    }
    if (idx < CC * CC) g_Wo[idx] = tf32r(wo[idx]);
    if (idx < YM) {
        float v;
        if (idx < CS)          v = bq[idx];
        else if (idx < 2 * CS) v = bk[idx - CS];
        else if (idx < M1)     v = bv[idx - 2 * CS];
        else                   v = 0.0f;
        g_bias[idx] = v;
    }
}

// ---------------- round x to tf32 copy ----------------
__global__ void roundx_kernel(const float* __restrict__ x)
{
    long i = ((long)blockIdx.x * blockDim.x + threadIdx.x) * 4;
    const long total = (long)BB * CC * HW;
    if (i >= total) return;
    float4 v = *(const float4*)(x + i);
    v.x = tf32r(v.x); v.y = tf32r(v.y); v.z = tf32r(v.z); v.w = tf32r(v.w);
    *(float4*)(g_Xr + i) = v;
}

// ---------------- tf32 tensor-core GEMM, 3-stage cp.async ----------------
// C[b] = A[b] @ B[b]. A row-major MxK, B row-major KxN, C row-major MxN.
// All operands PRE-ROUNDED to tf32 in gmem -> no cvt in the mainloop.
// BM=128, BN=256, BK=16. 256 threads = 8 warps (2x4); warp tile 64x64.
// HAS_RES: C = gamma*(acc + bias) + res.  ROUND_OUT: store tf32-rounded.
#define A_STRIDE 20            // 16 + 4 pad floats
#define B_STRIDE 260           // 256 + 4 pad floats
#define A_STAGE  (128 * A_STRIDE * 4)     // 10240 B
#define B_STAGE  (16 * B_STRIDE * 4)      // 16640 B
#define GEMM_SMEM (3 * (A_STAGE + B_STAGE))   // 80640 B

template<bool HAS_BIAS, bool HAS_RES, bool ROUND_OUT>
__global__ __launch_bounds__(256, 1)
void mma_gemm(int M, int N, int K,
              const float* __restrict__ A, long sA,
              const float* __restrict__ Bm, long sB,
              float* __restrict__ Cm, long sC,
              const float* __restrict__ bias,
              const float* __restrict__ res, long sR,
              const float* __restrict__ gamma_ptr)
{
    extern __shared__ float sm[];
    // layout: A stages [0..3), then B stages
    float* Asm = sm;                                  // 3 * 128 * A_STRIDE
    float* Bsm = sm + 3 * 128 * A_STRIDE;             // 3 * 16 * B_STRIDE

    int b = blockIdx.z;
    const float* Ab = A  + (long)b * sA;
    const float* Bb = Bm + (long)b * sB;
    float*       Cb = Cm + (long)b * sC;

    int m0 = blockIdx.y * 128;
    int n0 = blockIdx.x * 256;
    int t    = threadIdx.x;
    int warp = t >> 5;
    int lane = t & 31;
    int warpM = warp >> 2;       // 0..1
    int warpN = warp & 3;        // 0..3
    int grp = lane >> 2;         // 0..7
    int tig = lane & 3;          // 0..3

    // load coords: A 512 chunks (2/thread), B 1024 chunks (4/thread)
    int ar0 = t >> 2,         ac0 = (t & 3) * 4;       // A rows 0..63
    int ar1 = (t + 256) >> 2;                          // A rows 64..127
    int bk0 = t >> 4,         bc0 = (t & 15) * 16;     // B k 0..15, cols by 16

    float acc[4][8][4];
#pragma unroll
    for (int i = 0; i < 4; i++)
#pragma unroll
        for (int j = 0; j < 8; j++)
#pragma unroll
            for (int f = 0; f < 4; f++) acc[i][j][f] = 0.f;

    const int T = K / 16;

    auto load_tile = [&](int ti) {
        int s = ti % 3;
        int k0 = ti * 16;
        float* As = Asm + s * 128 * A_STRIDE;
        float* Bs = Bsm + s * 16 * B_STRIDE;
        cp16(As + ar0 * A_STRIDE + ac0, Ab + (long)(m0 + ar0) * K + k0 + ac0);
        cp16(As + ar1 * A_STRIDE + ac0, Ab + (long)(m0 + ar1) * K + k0 + ac0);
#pragma unroll
        for (int i = 0; i < 4; i++) {
            cp16(Bs + bk0 * B_STRIDE + bc0 + 4 * i,
                 Bb + (long)(k0 + bk0) * N + n0 + bc0 + 4 * i);
        }
        cp_commit();
    };

    load_tile(0);
    load_tile(1);

    for (int ti = 0; ti < T; ti++) {
        if (ti + 2 < T) load_tile(ti + 2);
        else            cp_commit();          // keep group count regular
        cp_wait<2>();
        __syncthreads();

        int s = ti % 3;
        const float* As = Asm + s * 128 * A_STRIDE;
        const float* Bs = Bsm + s * 16 * B_STRIDE;

#pragma unroll
        for (int kk = 0; kk < 16; kk += 8) {
            uint32_t af[4][4], bf[8][2];
#pragma unroll
            for (int mt = 0; mt < 4; mt++) {
                int m = warpM * 64 + mt * 16 + grp;
                af[mt][0] = __float_as_uint(As[(m    ) * A_STRIDE + kk + tig]);
                af[mt][1] = __float_as_uint(As[(m + 8) * A_STRIDE + kk + tig]);
                af[mt][2] = __float_as_uint(As[(m    ) * A_STRIDE + kk + tig + 4]);
                af[mt][3] = __float_as_uint(As[(m + 8) * A_STRIDE + kk + tig + 4]);
            }
#pragma unroll
            for (int nt = 0; nt < 8; nt++) {
                int n = warpN * 64 + nt * 8 + grp;
                bf[nt][0] = __float_as_uint(Bs[(kk + tig    ) * B_STRIDE + n]);
                bf[nt][1] = __float_as_uint(Bs[(kk + tig + 4) * B_STRIDE + n]);
            }
#pragma unroll
            for (int mt = 0; mt < 4; mt++)
#pragma unroll
                for (int nt = 0; nt < 8; nt++)
                    mma_tf32(acc[mt][nt][0], acc[mt][nt][1], acc[mt][nt][2], acc[mt][nt][3],
                             af[mt][0], af[mt][1], af[mt][2], af[mt][3],
                             bf[nt][0], bf[nt][1]);
        }
        __syncthreads();
    }

    float gm = 1.0f;
    if (HAS_RES) gm = *gamma_ptr;
    const float* resb = HAS_RES ? (res + (long)b * sR) : nullptr;

#pragma unroll
    for (int mt = 0; mt < 4; mt++) {
        int row0 = m0 + warpM * 64 + mt * 16 + grp;
        int row1 = row0 + 8;
        float bv0 = HAS_BIAS ? bias[row0] : 0.0f;
        float bv1 = HAS_BIAS ? bias[row1] : 0.0f;
#pragma unroll
        for (int nt = 0; nt < 8; nt++) {
            int col = n0 + warpN * 64 + nt * 8 + 2 * tig;
            long off0 = (long)row0 * N + col;
            long off1 = (long)row1 * N + col;
            float2 o0, o1;
            o0.x = acc[mt][nt][0] + bv0; o0.y = acc[mt][nt][1] + bv0;
            o1.x = acc[mt][nt][2] + bv1; o1.y = acc[mt][nt][3] + bv1;
            if (HAS_RES) {
                float2 r0 = *(const float2*)(resb + off0);
                float2 r1 = *(const float2*)(resb + off1);
                o0.x = gm * o0.x + r0.x;  o0.y = gm * o0.y + r0.y;
                o1.x = gm * o1.x + r1.x;  o1.y = gm * o1.y + r1.y;
            }
            if (ROUND_OUT) {
                o0.x = tf32r(o0.x); o0.y = tf32r(o0.y);
                o1.x = tf32r(o1.x); o1.y = tf32r(o1.y);
            }
            *(float2*)(Cb + off0) = o0;
            *(float2*)(Cb + off1) = o1;
        }
    }
}

// ---------------- maxpool Q (before energy) ----------------
__global__ void poolQ_kernel()
{
    long idx = (long)blockIdx.x * blockDim.x + threadIdx.x;
    const long total = (long)BB * CS * NP;
    if (idx >= total) return;
    int np = (int)(idx & (NP - 1));
    int c  = (int)((idx >> 10) % CS);
    int b  = (int)(idx / ((long)CS * NP));
    int hp = np >> 5, wp = np & 31;
    const float* src = g_Y + ((long)b * YM + c) * HW + (hp * 2) * 64 + wp * 2;
    float m = fmaxf(fmaxf(src[0], src[1]), fmaxf(src[64], src[65]));
    g_Q[((long)b * CS + c) * NP + np] = m;
}

// ---------------- maxpool V * invsum (after energy), tf32-rounded ----------------
__global__ void poolV_kernel()
{
    long idx = (long)blockIdx.x * blockDim.x + threadIdx.x;
    const long total = (long)BB * CC * NP;
    if (idx >= total) return;
    int np = (int)(idx & (NP - 1));
    int c  = (int)((idx >> 10) % CC);
    int b  = (int)(idx / ((long)CC * NP));
    int hp = np >> 5, wp = np & 31;
    const float* src = g_Y + ((long)b * YM + 2 * CS + c) * HW + (hp * 2) * 64 + wp * 2;
    float m = fmaxf(fmaxf(src[0], src[1]), fmaxf(src[64], src[65]));
    g_Vp[((long)b * CC + c) * NP + np] = tf32r(m * g_invsum[(long)b * NP + np]);
}

// ---------------- single-pass energy + exp + rowsum (fp32-exact E) ----------------
__global__ __launch_bounds__(256) void energy_kernel()
{
    int b  = blockIdx.y;
    int n0 = blockIdx.x * 32;
    const float* Kb = g_Y + ((long)b * YM + CS) * HW;
    const float* Qb = g_Q + (long)b * CS * NP;

    __shared__ float Qs[CS][33];
    __shared__ float Ks[CS][256];

    int t = threadIdx.x;
    int warp = t >> 5, lane = t & 31;

#pragma unroll
    for (int i = 0; i < 4; i++) {
        int idx = t + 256 * i;
        int c = idx >> 5, nl = idx & 31;
        Qs[c][nl] = Qb[(long)c * NP + n0 + nl];
    }
    __syncthreads();

    float rsum[4] = {0.f, 0.f, 0.f, 0.f};
    float* Pb = g_P + (long)b * NP * HW + (long)n0 * HW;

    for (int ch = 0; ch < 16; ch++) {
        int mbase = ch * 256;
#pragma unroll
        for (int i = 0; i < 8; i++) {
            int idx = t + 256 * i;
            int c = idx >> 6, c4 = (idx & 63) * 4;
            *(float4*)&Ks[c][c4] = *(const float4*)(Kb + (long)c * HW + mbase + c4);
        }
        __syncthreads();
        float e[4][8];
#pragma unroll
        for (int i = 0; i < 4; i++)
#pragma unroll
            for (int j = 0; j < 8; j++) e[i][j] = 0.f;
#pragma unroll
        for (int c = 0; c < CS; c++) {
            float q0 = Qs[c][warp * 4 + 0];
            float q1 = Qs[c][warp * 4 + 1];
            float q2 = Qs[c][warp * 4 + 2];
            float q3 = Qs[c][warp * 4 + 3];
#pragma unroll
            for (int j = 0; j < 8; j++) {
                float kv = Ks[c][lane + 32 * j];
                e[0][j] += q0 * kv;
                e[1][j] += q1 * kv;
                e[2][j] += q2 * kv;
                e[3][j] += q3 * kv;
            }
        }
#pragma unroll
        for (int i = 0; i < 4; i++) {
#pragma unroll
            for (int j = 0; j < 8; j++) {
                float p = tf32r(__expf(e[i][j]));
                rsum[i] += p;
                Pb[(long)(warp * 4 + i) * HW + mbase + lane + 32 * j] = p;
            }
        }
        __syncthreads();
    }
#pragma unroll
    for (int i = 0; i < 4; i++)
#pragma unroll
        for (int off = 16; off > 0; off >>= 1)
            rsum[i] += __shfl_xor_sync(0xffffffffu, rsum[i], off);
    if (lane == 0) {
#pragma unroll
        for (int i = 0; i < 4; i++)
            g_invsum[(long)b * NP + n0 + warp * 4 + i] = 1.0f / rsum[i];
    }
}

// ---------------- launch ----------------
extern "C" void kernel_launch(void* const* d_in, const int* in_sizes, int n_in,
                              void* d_out, int out_size)
{
    const float* x     = (const float*)d_in[0];
    const float* wq    = (const float*)d_in[1];
    const float* bq    = (const float*)d_in[2];
    const float* wk    = (const float*)d_in[3];
    const float* bk    = (const float*)d_in[4];
    const float* wv    = (const float*)d_in[5];
    const float* bv    = (const float*)d_in[6];
    const float* wo    = (const float*)d_in[7];
    const float* bo    = (const float*)d_in[8];
    const float* gamma = (const float*)d_in[9];
    float* out = (float*)d_out;

    float *pW, *pBias, *pWo, *pXr, *pY, *pVp, *pP, *pOut1;
    cudaGetSymbolAddress((void**)&pW,    g_W);
    cudaGetSymbolAddress((void**)&pBias, g_bias);
    cudaGetSymbolAddress((void**)&pWo,   g_Wo);
    cudaGetSymbolAddress((void**)&pXr,   g_Xr);
    cudaGetSymbolAddress((void**)&pY,    g_Y);
    cudaGetSymbolAddress((void**)&pVp,   g_Vp);
    cudaGetSymbolAddress((void**)&pP,    g_P);
    cudaGetSymbolAddress((void**)&pOut1, g_out1);

    cudaFuncSetAttribute(mma_gemm<true,  false, false>, cudaFuncAttributeMaxDynamicSharedMemorySize, GEMM_SMEM);
    cudaFuncSetAttribute(mma_gemm<false, false, true >, cudaFuncAttributeMaxDynamicSharedMemorySize, GEMM_SMEM);
    cudaFuncSetAttribute(mma_gemm<true,  true,  false>, cudaFuncAttributeMaxDynamicSharedMemorySize, GEMM_SMEM);

    // 1. pack + round weights; round x
    pack_kernel<<<(YM * CC + 255) / 256, 256>>>(wq, bq, wk, bk, wv, bv, wo);
    {
        long total4 = (long)BB * CC * HW / 4;
        roundx_kernel<<<(int)((total4 + 255) / 256), 256>>>(x);
    }

    // 2. QKV conv: Y[b] (384x4096) = W @ Xr[b] + bias   (fp32 output)
    {
        dim3 grid(HW / 256, YM / 128, BB);
        mma_gemm<true, false, false><<<grid, 256, GEMM_SMEM>>>(
            YM, HW, CC,
            pW, 0L,
            pXr, (long)CC * HW,
            pY, (long)YM * HW,
            pBias, nullptr, 0L, nullptr);
    }

    // 3. pool Q
    {
        long total = (long)BB * CS * NP;
        poolQ_kernel<<<(int)((total + 255) / 256), 256>>>();
    }

    // 4. energy + exp + rowsum -> P (tf32-rounded), invsum
    {
        dim3 grid(NP / 32, BB);
        energy_kernel<<<grid, 256>>>();
    }

    // 5. pool V with invsum folding (tf32-rounded)
    {
        long total = (long)BB * CC * NP;
        poolV_kernel<<<(int)((total + 255) / 256), 256>>>();
    }

    // 6. out1[b] (256x4096) = Vp[b] @ P[b]   (tf32-rounded output)
    {
        dim3 grid(HW / 256, CC / 128, BB);
        mma_gemm<false, false, true><<<grid, 256, GEMM_SMEM>>>(
            CC, HW, NP,
            pVp, (long)CC * NP,
            pP, (long)NP * HW,
            pOut1, (long)CC * HW,
            nullptr, nullptr, 0L, nullptr);
    }

    // 7. out[b] = gamma * (Wo @ out1[b] + bo) + x[b]
    {
        dim3 grid(HW / 256, CC / 128, BB);
        mma_gemm<true, true, false><<<grid, 256, GEMM_SMEM>>>(
            CC, HW, CC,
            pWo, 0L,
            pOut1, (long)CC * HW,
            out, (long)CC * HW,
            bo,
            x, (long)CC * HW,
            gamma);
    }
}

// round 9
// speedup vs baseline: 1.0939x; 1.0939x over previous
#include <cuda_runtime.h>
#include <cuda_bf16.h>
#include <math.h>
#include <stdint.h>

// Problem constants
#define BB   16
#define CC   256
#define HW   4096     // 64*64
#define CS   32
#define NP   1024     // 32*32
#define M1   320      // CS + CS + CC
#define YM   384      // M1 padded to multiple of 128

// ---------------- device scratch ----------------
__device__ float g_W[YM * CC];                  // packed [wq;wk;wv;0], tf32-rounded
__device__ float g_bias[YM];
__device__ float g_Wo[CC * CC];                 // wo, tf32-rounded
__device__ float g_Xr[(long)BB * CC * HW];      // x, tf32-rounded (GEMM1 B operand)
__device__ float g_Y[(long)BB * YM * HW];       // QKV conv outputs (fp32, exact for energy)
__device__ float g_Q[(long)BB * CS * NP];
__device__ float g_Vp[(long)BB * CC * NP];      // pooled V * invsum, tf32-rounded
__device__ float g_P[(long)BB * NP * HW];       // exp(E), tf32-rounded
__device__ float g_invsum[(long)BB * NP];
__device__ float g_out1[(long)BB * CC * HW];    // V' @ P, tf32-rounded

// ---------------- helpers ----------------
__device__ __forceinline__ float tf32r(float f) {
    uint32_t u;
    asm("cvt.rna.tf32.f32 %0, %1;" : "=r"(u) : "f"(f));
    return __uint_as_float(u);
}

__device__ __forceinline__ void mma_tf32(float& c0, float& c1, float& c2, float& c3,
                                         uint32_t a0, uint32_t a1, uint32_t a2, uint32_t a3,
                                         uint32_t b0, uint32_t b1)
{
    asm volatile(
        "mma.sync.aligned.m16n8k8.row.col.f32.tf32.tf32.f32 "
        "{%0,%1,%2,%3}, {%4,%5,%6,%7}, {%8,%9}, {%0,%1,%2,%3};\n"
        : "+f"(c0), "+f"(c1), "+f"(c2), "+f"(c3)
        : "r"(a0), "r"(a1), "r"(a2), "r"(a3), "r"(b0), "r"(b1));
}

__device__ __forceinline__ void cp16(void* smem, const void* gmem) {
    uint32_t sa = (uint32_t)__cvta_generic_to_shared(smem);
    asm volatile("cp.async.ca.shared.global [%0], [%1], 16;\n" :: "r"(sa), "l"(gmem));
}
__device__ __forceinline__ void cp_commit() { asm volatile("cp.async.commit_group;\n"); }
template<int N>
__device__ __forceinline__ void cp_wait() { asm volatile("cp.async.wait_group %0;\n" :: "n"(N)); }

// ---------------- pack weights (tf32-rounded) ----------------
__global__ void pack_kernel(const float* __restrict__ wq, const float* __restrict__ bq,
                            const float* __restrict__ wk, const float* __restrict__ bk,
                            const float* __restrict__ wv, const float* __restrict__ bv,
                            const float* __restrict__ wo)
{
    int idx = blockIdx.x * blockDim.x + threadIdx.x;
    if (idx < YM * CC) {
        int r = idx / CC, c = idx % CC;
        float v;
        if (r < CS)           v = wq[r * CC + c];
        else if (r < 2 * CS)  v = wk[(r - CS) * CC + c];
        else if (r < M1)      v = wv[(r - 2 * CS) * CC + c];
        else                  v = 0.0f;
        g_W[idx] = tf32r(v);
    }
    if (idx < CC * CC) g_Wo[idx] = tf32r(wo[idx]);
    if (idx < YM) {
        float v;
        if (idx < CS)          v = bq[idx];
        else if (idx < 2 * CS) v = bk[idx - CS];
        else if (idx < M1)     v = bv[idx - 2 * CS];
        else                   v = 0.0f;
        g_bias[idx] = v;
    }
}

// ---------------- round x to tf32 copy ----------------
__global__ void roundx_kernel(const float* __restrict__ x)
{
    long i = ((long)blockIdx.x * blockDim.x + threadIdx.x) * 4;
    const long total = (long)BB * CC * HW;
    if (i >= total) return;
    float4 v = *(const float4*)(x + i);
    v.x = tf32r(v.x); v.y = tf32r(v.y); v.z = tf32r(v.z); v.w = tf32r(v.w);
    *(float4*)(g_Xr + i) = v;
}

// ---------------- tf32 tensor-core GEMM, 3-stage cp.async ----------------
// C[b] = A[b] @ B[b]. A row-major MxK, B row-major KxN, C row-major MxN.
// All operands PRE-ROUNDED to tf32 in gmem -> no cvt in the mainloop.
// BM=128, BN=128, BK=16. 256 threads = 8 warps (2x4); warp tile 64x32.
// 2 CTAs/SM via launch_bounds. HAS_RES: C = gamma*(acc+bias)+res. ROUND_OUT: tf32 store.
#define A_STRIDE 20            // 16 + 4 pad floats
#define B_STRIDE 132           // 128 + 4 pad floats
#define A_STAGE_F (128 * A_STRIDE)        // floats
#define B_STAGE_F (16 * B_STRIDE)
#define GEMM_SMEM (3 * (A_STAGE_F + B_STAGE_F) * 4)   // 56448 B

template<bool HAS_BIAS, bool HAS_RES, bool ROUND_OUT>
__global__ __launch_bounds__(256, 2)
void mma_gemm(int M, int N, int K,
              const float* __restrict__ A, long sA,
              const float* __restrict__ Bm, long sB,
              float* __restrict__ Cm, long sC,
              const float* __restrict__ bias,
              const float* __restrict__ res, long sR,
              const float* __restrict__ gamma_ptr)
{
    extern __shared__ float sm[];
    float* Asm = sm;                                  // 3 * A_STAGE_F
    float* Bsm = sm + 3 * A_STAGE_F;                  // 3 * B_STAGE_F

    int b = blockIdx.z;
    const float* Ab = A  + (long)b * sA;
    const float* Bb = Bm + (long)b * sB;
    float*       Cb = Cm + (long)b * sC;

    int m0 = blockIdx.y * 128;
    int n0 = blockIdx.x * 128;
    int t    = threadIdx.x;
    int warp = t >> 5;
    int lane = t & 31;
    int warpM = warp >> 2;       // 0..1
    int warpN = warp & 3;        // 0..3
    int grp = lane >> 2;         // 0..7
    int tig = lane & 3;          // 0..3

    // load coords: A 512 f4 chunks (2/thread), B 512 f4 chunks (2/thread)
    int ar0 = t >> 2,         ac0 = (t & 3) * 4;       // A rows 0..63
    int ar1 = (t + 256) >> 2;                          // A rows 64..127
    int bk0 = t >> 5,         bc0 = (t & 31) * 4;      // B k 0..7
    int bk1 = (t + 256) >> 5;                          // B k 8..15

    float acc[4][4][4];
#pragma unroll
    for (int i = 0; i < 4; i++)
#pragma unroll
        for (int j = 0; j < 4; j++)
#pragma unroll
            for (int f = 0; f < 4; f++) acc[i][j][f] = 0.f;

    const int T = K / 16;

    auto load_tile = [&](int ti) {
        int s = ti % 3;
        int k0 = ti * 16;
        float* As = Asm + s * A_STAGE_F;
        float* Bs = Bsm + s * B_STAGE_F;
        cp16(As + ar0 * A_STRIDE + ac0, Ab + (long)(m0 + ar0) * K + k0 + ac0);
        cp16(As + ar1 * A_STRIDE + ac0, Ab + (long)(m0 + ar1) * K + k0 + ac0);
        cp16(Bs + bk0 * B_STRIDE + bc0, Bb + (long)(k0 + bk0) * N + n0 + bc0);
        cp16(Bs + bk1 * B_STRIDE + bc0, Bb + (long)(k0 + bk1) * N + n0 + bc0);
        cp_commit();
    };

    load_tile(0);
    load_tile(1);

    for (int ti = 0; ti < T; ti++) {
        if (ti + 2 < T) load_tile(ti + 2);
        else            cp_commit();          // keep group count regular
        cp_wait<2>();
        __syncthreads();

        int s = ti % 3;
        const float* As = Asm + s * A_STAGE_F;
        const float* Bs = Bsm + s * B_STAGE_F;

#pragma unroll
        for (int kk = 0; kk < 16; kk += 8) {
            uint32_t af[4][4], bf[4][2];
#pragma unroll
            for (int mt = 0; mt < 4; mt++) {
                int m = warpM * 64 + mt * 16 + grp;
                af[mt][0] = __float_as_uint(As[(m    ) * A_STRIDE + kk + tig]);
                af[mt][1] = __float_as_uint(As[(m + 8) * A_STRIDE + kk + tig]);
                af[mt][2] = __float_as_uint(As[(m    ) * A_STRIDE + kk + tig + 4]);
                af[mt][3] = __float_as_uint(As[(m + 8) * A_STRIDE + kk + tig + 4]);
            }
#pragma unroll
            for (int nt = 0; nt < 4; nt++) {
                int n = warpN * 32 + nt * 8 + grp;
                bf[nt][0] = __float_as_uint(Bs[(kk + tig    ) * B_STRIDE + n]);
                bf[nt][1] = __float_as_uint(Bs[(kk + tig + 4) * B_STRIDE + n]);
            }
#pragma unroll
            for (int mt = 0; mt < 4; mt++)
#pragma unroll
                for (int nt = 0; nt < 4; nt++)
                    mma_tf32(acc[mt][nt][0], acc[mt][nt][1], acc[mt][nt][2], acc[mt][nt][3],
                             af[mt][0], af[mt][1], af[mt][2], af[mt][3],
                             bf[nt][0], bf[nt][1]);
        }
        __syncthreads();
    }

    float gm = 1.0f;
    if (HAS_RES) gm = *gamma_ptr;
    const float* resb = HAS_RES ? (res + (long)b * sR) : nullptr;

#pragma unroll
    for (int mt = 0; mt < 4; mt++) {
        int row0 = m0 + warpM * 64 + mt * 16 + grp;
        int row1 = row0 + 8;
        float bv0 = HAS_BIAS ? bias[row0] : 0.0f;
        float bv1 = HAS_BIAS ? bias[row1] : 0.0f;
#pragma unroll
        for (int nt = 0; nt < 4; nt++) {
            int col = n0 + warpN * 32 + nt * 8 + 2 * tig;
            long off0 = (long)row0 * N + col;
            long off1 = (long)row1 * N + col;
            float2 o0, o1;
            o0.x = acc[mt][nt][0] + bv0; o0.y = acc[mt][nt][1] + bv0;
            o1.x = acc[mt][nt][2] + bv1; o1.y = acc[mt][nt][3] + bv1;
            if (HAS_RES) {
                float2 r0 = *(const float2*)(resb + off0);
                float2 r1 = *(const float2*)(resb + off1);
                o0.x = gm * o0.x + r0.x;  o0.y = gm * o0.y + r0.y;
                o1.x = gm * o1.x + r1.x;  o1.y = gm * o1.y + r1.y;
            }
            if (ROUND_OUT) {
                o0.x = tf32r(o0.x); o0.y = tf32r(o0.y);
                o1.x = tf32r(o1.x); o1.y = tf32r(o1.y);
            }
            *(float2*)(Cb + off0) = o0;
            *(float2*)(Cb + off1) = o1;
        }
    }
}

// ---------------- maxpool Q (before energy) ----------------
__global__ void poolQ_kernel()
{
    long idx = (long)blockIdx.x * blockDim.x + threadIdx.x;
    const long total = (long)BB * CS * NP;
    if (idx >= total) return;
    int np = (int)(idx & (NP - 1));
    int c  = (int)((idx >> 10) % CS);
    int b  = (int)(idx / ((long)CS * NP));
    int hp = np >> 5, wp = np & 31;
    const float* src = g_Y + ((long)b * YM + c) * HW + (hp * 2) * 64 + wp * 2;
    float m = fmaxf(fmaxf(src[0], src[1]), fmaxf(src[64], src[65]));
    g_Q[((long)b * CS + c) * NP + np] = m;
}

// ---------------- maxpool V * invsum (after energy), tf32-rounded ----------------
__global__ void poolV_kernel()
{
    long idx = (long)blockIdx.x * blockDim.x + threadIdx.x;
    const long total = (long)BB * CC * NP;
    if (idx >= total) return;
    int np = (int)(idx & (NP - 1));
    int c  = (int)((idx >> 10) % CC);
    int b  = (int)(idx / ((long)CC * NP));
    int hp = np >> 5, wp = np & 31;
    const float* src = g_Y + ((long)b * YM + 2 * CS + c) * HW + (hp * 2) * 64 + wp * 2;
    float m = fmaxf(fmaxf(src[0], src[1]), fmaxf(src[64], src[65]));
    g_Vp[((long)b * CC + c) * NP + np] = tf32r(m * g_invsum[(long)b * NP + np]);
}

// ---------------- single-pass energy + exp + rowsum (fp32-exact E) ----------------
// Lane owns 8 consecutive m-columns -> LDS.128 kv loads, STG.128 P stores.
__global__ __launch_bounds__(256) void energy_kernel()
{
    int b  = blockIdx.y;
    int n0 = blockIdx.x * 32;
    const float* Kb = g_Y + ((long)b * YM + CS) * HW;
    const float* Qb = g_Q + (long)b * CS * NP;

    __shared__ float Qs[CS][33];
    __shared__ float4 Ks4[CS][64];

    int t = threadIdx.x;
    int warp = t >> 5, lane = t & 31;

#pragma unroll
    for (int i = 0; i < 4; i++) {
        int idx = t + 256 * i;
        int c = idx >> 5, nl = idx & 31;
        Qs[c][nl] = Qb[(long)c * NP + n0 + nl];
    }
    __syncthreads();

    float rsum[4] = {0.f, 0.f, 0.f, 0.f};
    float* Pb = g_P + (long)b * NP * HW + (long)n0 * HW;

    for (int ch = 0; ch < 16; ch++) {
        int mbase = ch * 256;
#pragma unroll
        for (int i = 0; i < 8; i++) {
            int idx = t + 256 * i;            // 0..2047 float4 chunks
            int c = idx >> 6, c4 = idx & 63;
            Ks4[c][c4] = *(const float4*)(Kb + (long)c * HW + mbase + c4 * 4);
        }
        __syncthreads();
        float4 e[4][2];
#pragma unroll
        for (int i = 0; i < 4; i++) {
            e[i][0] = make_float4(0.f, 0.f, 0.f, 0.f);
            e[i][1] = make_float4(0.f, 0.f, 0.f, 0.f);
        }
#pragma unroll
        for (int c = 0; c < CS; c++) {
            float4 k0 = Ks4[c][lane * 2];
            float4 k1 = Ks4[c][lane * 2 + 1];
#pragma unroll
            for (int i = 0; i < 4; i++) {
                float q = Qs[c][warp * 4 + i];
                e[i][0].x += q * k0.x;  e[i][0].y += q * k0.y;
                e[i][0].z += q * k0.z;  e[i][0].w += q * k0.w;
                e[i][1].x += q * k1.x;  e[i][1].y += q * k1.y;
                e[i][1].z += q * k1.z;  e[i][1].w += q * k1.w;
            }
        }
#pragma unroll
        for (int i = 0; i < 4; i++) {
            float4 p0, p1;
            p0.x = tf32r(__expf(e[i][0].x));  p0.y = tf32r(__expf(e[i][0].y));
            p0.z = tf32r(__expf(e[i][0].z));  p0.w = tf32r(__expf(e[i][0].w));
            p1.x = tf32r(__expf(e[i][1].x));  p1.y = tf32r(__expf(e[i][1].y));
            p1.z = tf32r(__expf(e[i][1].z));  p1.w = tf32r(__expf(e[i][1].w));
            rsum[i] += (p0.x + p0.y + p0.z + p0.w) + (p1.x + p1.y + p1.z + p1.w);
            long base = (long)(warp * 4 + i) * HW + mbase + lane * 8;
            *(float4*)(Pb + base)     = p0;
            *(float4*)(Pb + base + 4) = p1;
        }
        __syncthreads();
    }
#pragma unroll
    for (int i = 0; i < 4; i++)
#pragma unroll
        for (int off = 16; off > 0; off >>= 1)
            rsum[i] += __shfl_xor_sync(0xffffffffu, rsum[i], off);
    if (lane == 0) {
#pragma unroll
        for (int i = 0; i < 4; i++)
            g_invsum[(long)b * NP + n0 + warp * 4 + i] = 1.0f / rsum[i];
    }
}

// ---------------- launch ----------------
extern "C" void kernel_launch(void* const* d_in, const int* in_sizes, int n_in,
                              void* d_out, int out_size)
{
    const float* x     = (const float*)d_in[0];
    const float* wq    = (const float*)d_in[1];
    const float* bq    = (const float*)d_in[2];
    const float* wk    = (const float*)d_in[3];
    const float* bk    = (const float*)d_in[4];
    const float* wv    = (const float*)d_in[5];
    const float* bv    = (const float*)d_in[6];
    const float* wo    = (const float*)d_in[7];
    const float* bo    = (const float*)d_in[8];
    const float* gamma = (const float*)d_in[9];
    float* out = (float*)d_out;

    float *pW, *pBias, *pWo, *pXr, *pY, *pVp, *pP, *pOut1;
    cudaGetSymbolAddress((void**)&pW,    g_W);
    cudaGetSymbolAddress((void**)&pBias, g_bias);
    cudaGetSymbolAddress((void**)&pWo,   g_Wo);
    cudaGetSymbolAddress((void**)&pXr,   g_Xr);
    cudaGetSymbolAddress((void**)&pY,    g_Y);
    cudaGetSymbolAddress((void**)&pVp,   g_Vp);
    cudaGetSymbolAddress((void**)&pP,    g_P);
    cudaGetSymbolAddress((void**)&pOut1, g_out1);

    cudaFuncSetAttribute(mma_gemm<true,  false, false>, cudaFuncAttributeMaxDynamicSharedMemorySize, GEMM_SMEM);
    cudaFuncSetAttribute(mma_gemm<false, false, true >, cudaFuncAttributeMaxDynamicSharedMemorySize, GEMM_SMEM);
    cudaFuncSetAttribute(mma_gemm<true,  true,  false>, cudaFuncAttributeMaxDynamicSharedMemorySize, GEMM_SMEM);

    // 1. pack + round weights; round x
    pack_kernel<<<(YM * CC + 255) / 256, 256>>>(wq, bq, wk, bk, wv, bv, wo);
    {
        long total4 = (long)BB * CC * HW / 4;
        roundx_kernel<<<(int)((total4 + 255) / 256), 256>>>(x);
    }

    // 2. QKV conv: Y[b] (384x4096) = W @ Xr[b] + bias   (fp32 output)
    {
        dim3 grid(HW / 128, YM / 128, BB);
        mma_gemm<true, false, false><<<grid, 256, GEMM_SMEM>>>(
            YM, HW, CC,
            pW, 0L,
            pXr, (long)CC * HW,
            pY, (long)YM * HW,
            pBias, nullptr, 0L, nullptr);
    }

    // 3. pool Q
    {
        long total = (long)BB * CS * NP;
        poolQ_kernel<<<(int)((total + 255) / 256), 256>>>();
    }

    // 4. energy + exp + rowsum -> P (tf32-rounded), invsum
    {
        dim3 grid(NP / 32, BB);
        energy_kernel<<<grid, 256>>>();
    }

    // 5. pool V with invsum folding (tf32-rounded)
    {
        long total = (long)BB * CC * NP;
        poolV_kernel<<<(int)((total + 255) / 256), 256>>>();
    }

    // 6. out1[b] (256x4096) = Vp[b] @ P[b]   (tf32-rounded output)
    {
        dim3 grid(HW / 128, CC / 128, BB);
        mma_gemm<false, false, true><<<grid, 256, GEMM_SMEM>>>(
            CC, HW, NP,
            pVp, (long)CC * NP,
            pP, (long)NP * HW,
            pOut1, (long)CC * HW,
            nullptr, nullptr, 0L, nullptr);
    }

    // 7. out[b] = gamma * (Wo @ out1[b] + bo) + x[b]
    {
        dim3 grid(HW / 128, CC / 128, BB);
        mma_gemm<true, true, false><<<grid, 256, GEMM_SMEM>>>(
            CC, HW, CC,
            pWo, 0L,
            pOut1, (long)CC * HW,
            out, (long)CC * HW,
            bo,
            x, (long)CC * HW,
            gamma);
    }
}

// round 12
// speedup vs baseline: 1.5824x; 1.4466x over previous
#include <cuda_runtime.h>
#include <cuda_fp16.h>
#include <cuda_bf16.h>
#include <math.h>
#include <stdint.h>

// Problem constants
#define BB   16
#define CC   256
#define HW   4096     // 64*64
#define CS   32
#define NP   1024     // 32*32
#define M1   320      // CS + CS + CC
#define YM   384      // M1 padded to multiple of 128

// ---------------- device scratch ----------------
__device__ __half g_Wh[YM * CC];                 // packed [wq;wk;wv;0] fp16
__device__ float  g_bias[YM];
__device__ __half g_Woh[CC * CC];                // wo fp16
__device__ __half g_Xh[(long)BB * CC * HW];      // x fp16
__device__ float  g_Y[(long)BB * YM * HW];       // QKV conv outputs (fp32, exact energy)
__device__ float  g_Q[(long)BB * CS * NP];       // pooled Q fp32
__device__ float  g_M[(long)BB * NP];            // per-row max of E (from tf32 MMA pass)
__device__ __half g_Ph[(long)BB * NP * HW];      // exp(E - M) fp16  (134 MB)
__device__ float  g_invsum[(long)BB * NP];
__device__ __half g_Vph[(long)BB * CC * NP];     // pooled V * invsum fp16
__device__ __half g_out1h[(long)BB * CC * HW];   // V' @ P fp16

// ---------------- PTX helpers ----------------
__device__ __forceinline__ void mma_tf32(float& c0, float& c1, float& c2, float& c3,
                                         uint32_t a0, uint32_t a1, uint32_t a2, uint32_t a3,
                                         uint32_t b0, uint32_t b1)
{
    asm volatile(
        "mma.sync.aligned.m16n8k8.row.col.f32.tf32.tf32.f32 "
        "{%0,%1,%2,%3}, {%4,%5,%6,%7}, {%8,%9}, {%0,%1,%2,%3};\n"
        : "+f"(c0), "+f"(c1), "+f"(c2), "+f"(c3)
        : "r"(a0), "r"(a1), "r"(a2), "r"(a3), "r"(b0), "r"(b1));
}

__device__ __forceinline__ void mma_f16(float& c0, float& c1, float& c2, float& c3,
                                        uint32_t a0, uint32_t a1, uint32_t a2, uint32_t a3,
                                        uint32_t b0, uint32_t b1)
{
    asm volatile(
        "mma.sync.aligned.m16n8k16.row.col.f32.f16.f16.f32 "
        "{%0,%1,%2,%3}, {%4,%5,%6,%7}, {%8,%9}, {%0,%1,%2,%3};\n"
        : "+f"(c0), "+f"(c1), "+f"(c2), "+f"(c3)
        : "r"(a0), "r"(a1), "r"(a2), "r"(a3), "r"(b0), "r"(b1));
}

__device__ __forceinline__ void ldsm_x4(uint32_t& r0, uint32_t& r1, uint32_t& r2, uint32_t& r3,
                                        uint32_t addr)
{
    asm volatile("ldmatrix.sync.aligned.m8n8.x4.shared.b16 {%0,%1,%2,%3}, [%4];"
                 : "=r"(r0), "=r"(r1), "=r"(r2), "=r"(r3) : "r"(addr));
}
__device__ __forceinline__ void ldsm_x2_t(uint32_t& r0, uint32_t& r1, uint32_t addr)
{
    asm volatile("ldmatrix.sync.aligned.m8n8.x2.trans.shared.b16 {%0,%1}, [%2];"
                 : "=r"(r0), "=r"(r1) : "r"(addr));
}

__device__ __forceinline__ void cp16s(uint32_t s, const void* g) {
    asm volatile("cp.async.ca.shared.global [%0], [%1], 16;\n" :: "r"(s), "l"(g));
}
__device__ __forceinline__ void cp16(void* smem, const void* gmem) {
    uint32_t sa = (uint32_t)__cvta_generic_to_shared(smem);
    cp16s(sa, gmem);
}
__device__ __forceinline__ void cp_commit() { asm volatile("cp.async.commit_group;\n"); }
template<int N>
__device__ __forceinline__ void cp_wait() { asm volatile("cp.async.wait_group %0;\n" :: "n"(N)); }

// ---------------- pack weights to fp16 ----------------
__global__ void pack_kernel(const float* __restrict__ wq, const float* __restrict__ bq,
                            const float* __restrict__ wk, const float* __restrict__ bk,
                            const float* __restrict__ wv, const float* __restrict__ bv,
                            const float* __restrict__ wo)
{
    int idx = blockIdx.x * blockDim.x + threadIdx.x;
    if (idx < YM * CC) {
        int r = idx / CC, c = idx % CC;
        float v;
        if (r < CS)           v = wq[r * CC + c];
        else if (r < 2 * CS)  v = wk[(r - CS) * CC + c];
        else if (r < M1)      v = wv[(r - 2 * CS) * CC + c];
        else                  v = 0.0f;
        g_Wh[idx] = __float2half(v);
    }
    if (idx < CC * CC) g_Woh[idx] = __float2half(wo[idx]);
    if (idx < YM) {
        float v;
        if (idx < CS)          v = bq[idx];
        else if (idx < 2 * CS) v = bk[idx - CS];
        else if (idx < M1)     v = bv[idx - 2 * CS];
        else                   v = 0.0f;
        g_bias[idx] = v;
    }
}

// ---------------- x -> fp16 ----------------
__global__ void cvtx_kernel(const float* __restrict__ x)
{
    long i = ((long)blockIdx.x * blockDim.x + threadIdx.x) * 8;
    const long total = (long)BB * CC * HW;
    if (i >= total) return;
    float4 v0 = *(const float4*)(x + i);
    float4 v1 = *(const float4*)(x + i + 4);
    union { __half2 h[4]; uint4 u; } U;
    U.h[0] = __floats2half2_rn(v0.x, v0.y);
    U.h[1] = __floats2half2_rn(v0.z, v0.w);
    U.h[2] = __floats2half2_rn(v1.x, v1.y);
    U.h[3] = __floats2half2_rn(v1.z, v1.w);
    *(uint4*)(g_Xh + i) = U.u;
}

// ---------------- fp16 tensor-core GEMM, 3-stage cp.async + ldmatrix ----------------
// C[b] = A[b] @ B[b]. A row-major MxK fp16, B row-major KxN fp16 (k-major = mma col-major).
// BM=128, BN=128, BK=32. 256 thr = 8 warps (2x4); warp tile 64x32. 2 CTAs/SM.
#define AST 40        // A smem row stride (halfs): 32 + 8
#define BST 136       // B smem row stride (halfs): 128 + 8
#define A_STG (128 * AST)   // 5120 halfs
#define B_STG (32 * BST)    // 4352 halfs
#define H_SMEM (3 * (A_STG + B_STG) * 2)   // 56832 B

template<bool HAS_BIAS, bool HAS_RES, bool OUT_HALF>
__global__ __launch_bounds__(256, 2)
void hgemm(int M, int N, int K,
           const __half* __restrict__ A, long sA,
           const __half* __restrict__ Bm, long sB,
           void* __restrict__ Cm, long sC,
           const float* __restrict__ bias,
           const float* __restrict__ res, long sR,
           const float* __restrict__ gamma_ptr)
{
    extern __shared__ __half hsm[];
    uint32_t s0 = (uint32_t)__cvta_generic_to_shared(hsm);

    int b = blockIdx.z;
    const __half* Ab = A  + (long)b * sA;
    const __half* Bb = Bm + (long)b * sB;

    int m0 = blockIdx.y * 128;
    int n0 = blockIdx.x * 128;
    int t    = threadIdx.x;
    int warp = t >> 5;
    int lane = t & 31;
    int warpM = warp >> 2;       // 0..1
    int warpN = warp & 3;        // 0..3
    int grp = lane >> 2;         // 0..7
    int tig = lane & 3;          // 0..3

    // cp.async coords
    int ar0 = t >> 2,  ac0 = (t & 3) * 8;    // A rows 0..63
    int ar1 = ar0 + 64;                      // A rows 64..127
    int br0 = t >> 4,  bc0 = (t & 15) * 8;   // B k 0..15
    int br1 = br0 + 16;                      // B k 16..31

    // ldmatrix lane offsets (bytes, relative to stage base)
    uint32_t aLane = (uint32_t)(((warpM * 64 + (lane & 15)) * AST + (lane >> 4) * 8) * 2);
    uint32_t bLane = (uint32_t)(((lane & 15) * BST + warpN * 32) * 2);

    float acc[4][4][4];
#pragma unroll
    for (int i = 0; i < 4; i++)
#pragma unroll
        for (int j = 0; j < 4; j++)
#pragma unroll
            for (int f = 0; f < 4; f++) acc[i][j][f] = 0.f;

    const int T = K / 32;

    auto load_tile = [&](int ti) {
        int s = ti % 3;
        int k0 = ti * 32;
        uint32_t ab = s0 + (uint32_t)(s * (A_STG + B_STG) * 2);
        uint32_t bb = ab + A_STG * 2;
        cp16s(ab + (ar0 * AST + ac0) * 2, Ab + (long)(m0 + ar0) * K + k0 + ac0);
        cp16s(ab + (ar1 * AST + ac0) * 2, Ab + (long)(m0 + ar1) * K + k0 + ac0);
        cp16s(bb + (br0 * BST + bc0) * 2, Bb + (long)(k0 + br0) * N + n0 + bc0);
        cp16s(bb + (br1 * BST + bc0) * 2, Bb + (long)(k0 + br1) * N + n0 + bc0);
        cp_commit();
    };

    load_tile(0);
    load_tile(1);

    for (int ti = 0; ti < T; ti++) {
        if (ti + 2 < T) load_tile(ti + 2);
        else            cp_commit();
        cp_wait<2>();
        __syncthreads();

        int s = ti % 3;
        uint32_t ab = s0 + (uint32_t)(s * (A_STG + B_STG) * 2);
        uint32_t aBase = ab + aLane;
        uint32_t bBase = ab + A_STG * 2 + bLane;

#pragma unroll
        for (int kb = 0; kb < 32; kb += 16) {
            uint32_t af[4][4], bf[4][2];
#pragma unroll
            for (int mt = 0; mt < 4; mt++)
                ldsm_x4(af[mt][0], af[mt][1], af[mt][2], af[mt][3],
                        aBase + (uint32_t)((mt * 16 * AST + kb) * 2));
#pragma unroll
            for (int nt = 0; nt < 4; nt++)
                ldsm_x2_t(bf[nt][0], bf[nt][1],
                          bBase + (uint32_t)((kb * BST + nt * 8) * 2));
#pragma unroll
            for (int mt = 0; mt < 4; mt++)
#pragma unroll
                for (int nt = 0; nt < 4; nt++)
                    mma_f16(acc[mt][nt][0], acc[mt][nt][1], acc[mt][nt][2], acc[mt][nt][3],
                            af[mt][0], af[mt][1], af[mt][2], af[mt][3],
                            bf[nt][0], bf[nt][1]);
        }
        __syncthreads();
    }

    float gm = 1.0f;
    if (HAS_RES) gm = *gamma_ptr;
    const float* resb = HAS_RES ? (res + (long)b * sR) : nullptr;

#pragma unroll
    for (int mt = 0; mt < 4; mt++) {
        int row0 = m0 + warpM * 64 + mt * 16 + grp;
        int row1 = row0 + 8;
        float bv0 = HAS_BIAS ? bias[row0] : 0.0f;
        float bv1 = HAS_BIAS ? bias[row1] : 0.0f;
#pragma unroll
        for (int nt = 0; nt < 4; nt++) {
            int col = n0 + warpN * 32 + nt * 8 + 2 * tig;
            long off0 = (long)row0 * N + col;
            long off1 = (long)row1 * N + col;
            float2 o0, o1;
            o0.x = acc[mt][nt][0] + bv0; o0.y = acc[mt][nt][1] + bv0;
            o1.x = acc[mt][nt][2] + bv1; o1.y = acc[mt][nt][3] + bv1;
            if (HAS_RES) {
                float2 r0 = *(const float2*)(resb + off0);
                float2 r1 = *(const float2*)(resb + off1);
                o0.x = gm * o0.x + r0.x;  o0.y = gm * o0.y + r0.y;
                o1.x = gm * o1.x + r1.x;  o1.y = gm * o1.y + r1.y;
            }
            if (OUT_HALF) {
                __half* Ch = (__half*)Cm + (long)b * sC;
                *(__half2*)(Ch + off0) = __floats2half2_rn(o0.x, o0.y);
                *(__half2*)(Ch + off1) = __floats2half2_rn(o1.x, o1.y);
            } else {
                float* Cf = (float*)Cm + (long)b * sC;
                *(float2*)(Cf + off0) = o0;
                *(float2*)(Cf + off1) = o1;
            }
        }
    }
}

// ---------------- maxpool Q ----------------
__global__ void poolQ_kernel()
{
    long idx = (long)blockIdx.x * blockDim.x + threadIdx.x;
    const long total = (long)BB * CS * NP;
    if (idx >= total) return;
    int np = (int)(idx & (NP - 1));
    int c  = (int)((idx >> 10) % CS);
    int b  = (int)(idx / ((long)CS * NP));
    int hp = np >> 5, wp = np & 31;
    const float* src = g_Y + ((long)b * YM + c) * HW + (hp * 2) * 64 + wp * 2;
    float m = fmaxf(fmaxf(src[0], src[1]), fmaxf(src[64], src[65]));
    g_Q[((long)b * CS + c) * NP + np] = m;
}

// ---------------- maxpool V * invsum -> fp16 ----------------
__global__ void poolV_kernel()
{
    long idx = (long)blockIdx.x * blockDim.x + threadIdx.x;
    const long total = (long)BB * CC * NP;
    if (idx >= total) return;
    int np = (int)(idx & (NP - 1));
    int c  = (int)((idx >> 10) % CC);
    int b  = (int)(idx / ((long)CC * NP));
    int hp = np >> 5, wp = np & 31;
    const float* src = g_Y + ((long)b * YM + 2 * CS + c) * HW + (hp * 2) * 64 + wp * 2;
    float m = fmaxf(fmaxf(src[0], src[1]), fmaxf(src[64], src[65]));
    g_Vph[((long)b * CC + c) * NP + np] = __float2half(m * g_invsum[(long)b * NP + np]);
}

// ---------------- rowmax of E via tf32 MMA (max only, no store) ----------------
// E[n,m] = sum_c Q[c,n] * K[c,m].  Block: 128 n-rows x all 4096 m. 256 thr.
#define MX_SMEM ((32 * 132 + 2 * 32 * 132 + 128 * 4) * 4)

__global__ __launch_bounds__(256) void maxE_kernel()
{
    extern __shared__ float sm[];
    float* Qs = sm;                        // [32][132]
    float* Ks = sm + 32 * 132;             // [2][32][132]
    float* Rm = Ks + 2 * 32 * 132;         // [128][4]

    int b  = blockIdx.y;
    int n0 = blockIdx.x * 128;
    const float* Qb = g_Q + (long)b * CS * NP;
    const float* Kb = g_Y + ((long)b * YM + CS) * HW;

    int t = threadIdx.x;
    int warp = t >> 5, lane = t & 31;
    int warpM = warp >> 2, warpN = warp & 3;
    int grp = lane >> 2, tig = lane & 3;
    int nw = warpM * 64;

#pragma unroll
    for (int i = 0; i < 4; i++) {
        int idx = t + 256 * i;                 // 1024 float4 chunks
        int c = idx >> 5, n4 = (idx & 31) * 4;
        *(float4*)&Qs[c * 132 + n4] = *(const float4*)(Qb + (long)c * NP + n0 + n4);
    }

    auto loadK = [&](int ch, int buf) {
#pragma unroll
        for (int i = 0; i < 4; i++) {
            int idx = t + 256 * i;
            int c = idx >> 5, m4 = (idx & 31) * 4;
            cp16(&Ks[buf * 32 * 132 + c * 132 + m4], Kb + (long)c * HW + ch * 128 + m4);
        }
        cp_commit();
    };

    loadK(0, 0);
    __syncthreads();   // Qs ready

    float rmax[4][2];
#pragma unroll
    for (int i = 0; i < 4; i++) { rmax[i][0] = -1e30f; rmax[i][1] = -1e30f; }

    for (int ch = 0; ch < 32; ch++) {
        int buf = ch & 1;
        if (ch + 1 < 32) { loadK(ch + 1, buf ^ 1); cp_wait<1>(); }
        else             { cp_wait<0>(); }
        __syncthreads();
        const float* Kc = Ks + buf * 32 * 132;

        float acc[4][4][4];
#pragma unroll
        for (int i = 0; i < 4; i++)
#pragma unroll
            for (int j = 0; j < 4; j++)
#pragma unroll
                for (int f = 0; f < 4; f++) acc[i][j][f] = 0.f;

#pragma unroll
        for (int kk = 0; kk < 32; kk += 8) {
            uint32_t af[4][4], bf[4][2];
#pragma unroll
            for (int mt = 0; mt < 4; mt++) {
                int n = nw + mt * 16 + grp;
                af[mt][0] = __float_as_uint(Qs[(kk + tig    ) * 132 + n]);
                af[mt][1] = __float_as_uint(Qs[(kk + tig    ) * 132 + n + 8]);
                af[mt][2] = __float_as_uint(Qs[(kk + tig + 4) * 132 + n]);
                af[mt][3] = __float_as_uint(Qs[(kk + tig + 4) * 132 + n + 8]);
            }
#pragma unroll
            for (int nt = 0; nt < 4; nt++) {
                int m = warpN * 32 + nt * 8 + grp;
                bf[nt][0] = __float_as_uint(Kc[(kk + tig    ) * 132 + m]);
                bf[nt][1] = __float_as_uint(Kc[(kk + tig + 4) * 132 + m]);
            }
#pragma unroll
            for (int mt = 0; mt < 4; mt++)
#pragma unroll
                for (int nt = 0; nt < 4; nt++)
                    mma_tf32(acc[mt][nt][0], acc[mt][nt][1], acc[mt][nt][2], acc[mt][nt][3],
                             af[mt][0], af[mt][1], af[mt][2], af[mt][3],
                             bf[nt][0], bf[nt][1]);
        }
#pragma unroll
        for (int mt = 0; mt < 4; mt++)
#pragma unroll
            for (int nt = 0; nt < 4; nt++) {
                rmax[mt][0] = fmaxf(rmax[mt][0], fmaxf(acc[mt][nt][0], acc[mt][nt][1]));
                rmax[mt][1] = fmaxf(rmax[mt][1], fmaxf(acc[mt][nt][2], acc[mt][nt][3]));
            }
        __syncthreads();
    }

    // reduce across the 4 tig lanes sharing a row
#pragma unroll
    for (int mt = 0; mt < 4; mt++)
#pragma unroll
        for (int h = 0; h < 2; h++) {
            float v = rmax[mt][h];
            v = fmaxf(v, __shfl_xor_sync(0xffffffffu, v, 1));
            v = fmaxf(v, __shfl_xor_sync(0xffffffffu, v, 2));
            if (tig == 0) {
                int row = nw + mt * 16 + grp + h * 8;
                Rm[row * 4 + warpN] = v;
            }
        }
    __syncthreads();
    if (t < 128) {
        float v = fmaxf(fmaxf(Rm[t * 4 + 0], Rm[t * 4 + 1]),
                        fmaxf(Rm[t * 4 + 2], Rm[t * 4 + 3]));
        g_M[(long)b * NP + n0 + t] = v;
    }
}

// ---------------- energy: exact fp32 E, exp(E - M), fp16 store, rowsum ----------------
__global__ __launch_bounds__(256) void energy_kernel()
{
    int b  = blockIdx.y;
    int n0 = blockIdx.x * 32;
    const float* Kb = g_Y + ((long)b * YM + CS) * HW;
    const float* Qb = g_Q + (long)b * CS * NP;

    __shared__ float Qs[CS][33];
    __shared__ float4 Ks4[CS][64];

    int t = threadIdx.x;
    int warp = t >> 5, lane = t & 31;

#pragma unroll
    for (int i = 0; i < 4; i++) {
        int idx = t + 256 * i;
        int c = idx >> 5, nl = idx & 31;
        Qs[c][nl] = Qb[(long)c * NP + n0 + nl];
    }
    __syncthreads();

    float mrow[4];
#pragma unroll
    for (int i = 0; i < 4; i++) mrow[i] = g_M[(long)b * NP + n0 + warp * 4 + i];

    float rsum[4] = {0.f, 0.f, 0.f, 0.f};
    __half* Pb = g_Ph + (long)b * NP * HW + (long)n0 * HW;

    for (int ch = 0; ch < 16; ch++) {
        int mbase = ch * 256;
#pragma unroll
        for (int i = 0; i < 8; i++) {
            int idx = t + 256 * i;
            int c = idx >> 6, c4 = idx & 63;
            Ks4[c][c4] = *(const float4*)(Kb + (long)c * HW + mbase + c4 * 4);
        }
        __syncthreads();
        float4 e[4][2];
#pragma unroll
        for (int i = 0; i < 4; i++) {
            e[i][0] = make_float4(0.f, 0.f, 0.f, 0.f);
            e[i][1] = make_float4(0.f, 0.f, 0.f, 0.f);
        }
#pragma unroll
        for (int c = 0; c < CS; c++) {
            float4 k0 = Ks4[c][lane * 2];
            float4 k1 = Ks4[c][lane * 2 + 1];
#pragma unroll
            for (int i = 0; i < 4; i++) {
                float q = Qs[c][warp * 4 + i];
                e[i][0].x += q * k0.x;  e[i][0].y += q * k0.y;
                e[i][0].z += q * k0.z;  e[i][0].w += q * k0.w;
                e[i][1].x += q * k1.x;  e[i][1].y += q * k1.y;
                e[i][1].z += q * k1.z;  e[i][1].w += q * k1.w;
            }
        }
#pragma unroll
        for (int i = 0; i < 4; i++) {
            float p0 = __expf(e[i][0].x - mrow[i]);
            float p1 = __expf(e[i][0].y - mrow[i]);
            float p2 = __expf(e[i][0].z - mrow[i]);
            float p3 = __expf(e[i][0].w - mrow[i]);
            float p4 = __expf(e[i][1].x - mrow[i]);
            float p5 = __expf(e[i][1].y - mrow[i]);
            float p6 = __expf(e[i][1].z - mrow[i]);
            float p7 = __expf(e[i][1].w - mrow[i]);
            rsum[i] += (p0 + p1 + p2 + p3) + (p4 + p5 + p6 + p7);
            union { __half2 h[4]; uint4 u; } U;
            U.h[0] = __floats2half2_rn(p0, p1);
            U.h[1] = __floats2half2_rn(p2, p3);
            U.h[2] = __floats2half2_rn(p4, p5);
            U.h[3] = __floats2half2_rn(p6, p7);
            long base = (long)(warp * 4 + i) * HW + mbase + lane * 8;
            *(uint4*)(Pb + base) = U.u;
        }
        __syncthreads();
    }
#pragma unroll
    for (int i = 0; i < 4; i++)
#pragma unroll
        for (int off = 16; off > 0; off >>= 1)
            rsum[i] += __shfl_xor_sync(0xffffffffu, rsum[i], off);
    if (lane == 0) {
#pragma unroll
        for (int i = 0; i < 4; i++)
            g_invsum[(long)b * NP + n0 + warp * 4 + i] = 1.0f / rsum[i];
    }
}

// ---------------- launch ----------------
extern "C" void kernel_launch(void* const* d_in, const int* in_sizes, int n_in,
                              void* d_out, int out_size)
{
    const float* x     = (const float*)d_in[0];
    const float* wq    = (const float*)d_in[1];
    const float* bq    = (const float*)d_in[2];
    const float* wk    = (const float*)d_in[3];
    const float* bk    = (const float*)d_in[4];
    const float* wv    = (const float*)d_in[5];
    const float* bv    = (const float*)d_in[6];
    const float* wo    = (const float*)d_in[7];
    const float* bo    = (const float*)d_in[8];
    const float* gamma = (const float*)d_in[9];
    float* out = (float*)d_out;

    __half *pWh, *pWoh, *pXh, *pPh, *pVph, *pOut1h;
    float *pBias, *pY;
    cudaGetSymbolAddress((void**)&pWh,    g_Wh);
    cudaGetSymbolAddress((void**)&pBias,  g_bias);
    cudaGetSymbolAddress((void**)&pWoh,   g_Woh);
    cudaGetSymbolAddress((void**)&pXh,    g_Xh);
    cudaGetSymbolAddress((void**)&pY,     g_Y);
    cudaGetSymbolAddress((void**)&pPh,    g_Ph);
    cudaGetSymbolAddress((void**)&pVph,   g_Vph);
    cudaGetSymbolAddress((void**)&pOut1h, g_out1h);

    cudaFuncSetAttribute(hgemm<true,  false, false>, cudaFuncAttributeMaxDynamicSharedMemorySize, H_SMEM);
    cudaFuncSetAttribute(hgemm<false, false, true >, cudaFuncAttributeMaxDynamicSharedMemorySize, H_SMEM);
    cudaFuncSetAttribute(hgemm<true,  true,  false>, cudaFuncAttributeMaxDynamicSharedMemorySize, H_SMEM);
    cudaFuncSetAttribute(maxE_kernel, cudaFuncAttributeMaxDynamicSharedMemorySize, MX_SMEM);

    // 1. pack weights; convert x
    pack_kernel<<<(YM * CC + 255) / 256, 256>>>(wq, bq, wk, bk, wv, bv, wo);
    {
        long total8 = (long)BB * CC * HW / 8;
        cvtx_kernel<<<(int)((total8 + 255) / 256), 256>>>(x);
    }

    // 2. QKV conv: Y[b] (384x4096) = Wh @ Xh[b] + bias (fp32 out)
    {
        dim3 grid(HW / 128, YM / 128, BB);
        hgemm<true, false, false><<<grid, 256, H_SMEM>>>(
            YM, HW, CC,
            pWh, 0L,
            pXh, (long)CC * HW,
            pY, (long)YM * HW,
            pBias, nullptr, 0L, nullptr);
    }

    // 3. pool Q
    {
        long total = (long)BB * CS * NP;
        poolQ_kernel<<<(int)((total + 255) / 256), 256>>>();
    }

    // 4. rowmax of E (tf32 MMA)
    {
        dim3 grid(NP / 128, BB);
        maxE_kernel<<<grid, 256, MX_SMEM>>>();
    }

    // 5. energy: exact E, P = exp(E - M) fp16, invsum
    {
        dim3 grid(NP / 32, BB);
        energy_kernel<<<grid, 256>>>();
    }

    // 6. pool V with invsum folding -> fp16
    {
        long total = (long)BB * CC * NP;
        poolV_kernel<<<(int)((total + 255) / 256), 256>>>();
    }

    // 7. out1[b] (256x4096) = Vph[b] @ Ph[b]  (fp16 out)
    {
        dim3 grid(HW / 128, CC / 128, BB);
        hgemm<false, false, true><<<grid, 256, H_SMEM>>>(
            CC, HW, NP,
            pVph, (long)CC * NP,
            pPh, (long)NP * HW,
            pOut1h, (long)CC * HW,
            nullptr, nullptr, 0L, nullptr);
    }

    // 8. out[b] = gamma * (Woh @ out1h[b] + bo) + x[b]  (fp32 out)
    {
        dim3 grid(HW / 128, CC / 128, BB);
        hgemm<true, true, false><<<grid, 256, H_SMEM>>>(
            CC, HW, CC,
            pWoh, 0L,
            pOut1h, (long)CC * HW,
            out, (long)CC * HW,
            bo,
            x, (long)CC * HW,
            gamma);
    }
}

// round 15
// speedup vs baseline: 2.3118x; 1.4609x over previous
#include <cuda_runtime.h>
#include <cuda_fp16.h>
#include <math.h>
#include <stdint.h>

// Problem constants
#define BB   16
#define CC   256
#define HW   4096     // 64*64
#define CS   32
#define NP   1024     // 32*32
#define M1   320      // CS + CS + CC
#define YM   384      // M1 padded to multiple of 128

// ---------------- device scratch ----------------
__device__ __half g_Wh[YM * CC];                 // packed [wq;wk;wv;0] fp16
__device__ float  g_bias[YM];
__device__ __half g_Woh[CC * CC];                // wo fp16
__device__ __half g_Xh[(long)BB * CC * HW];      // x fp16
__device__ __half g_Yh[(long)BB * YM * HW];      // QKV conv outputs fp16 (42 MB)
__device__ __half g_Qt[(long)BB * NP * CS];      // pooled Q, TRANSPOSED [b][n][c] fp16
__device__ float  g_M[(long)BB * NP];            // per-row max of E
__device__ __half g_Ph[(long)BB * NP * HW];      // exp(E - M) fp16 (134 MB)
__device__ float  g_invsum[(long)BB * NP];
__device__ __half g_Vph[(long)BB * CC * NP];     // pooled V * invsum fp16
__device__ __half g_out1h[(long)BB * CC * HW];   // V' @ P fp16

// ---------------- PTX helpers ----------------
__device__ __forceinline__ void mma_f16(float& c0, float& c1, float& c2, float& c3,
                                        uint32_t a0, uint32_t a1, uint32_t a2, uint32_t a3,
                                        uint32_t b0, uint32_t b1)
{
    asm volatile(
        "mma.sync.aligned.m16n8k16.row.col.f32.f16.f16.f32 "
        "{%0,%1,%2,%3}, {%4,%5,%6,%7}, {%8,%9}, {%0,%1,%2,%3};\n"
        : "+f"(c0), "+f"(c1), "+f"(c2), "+f"(c3)
        : "r"(a0), "r"(a1), "r"(a2), "r"(a3), "r"(b0), "r"(b1));
}

__device__ __forceinline__ void ldsm_x4(uint32_t& r0, uint32_t& r1, uint32_t& r2, uint32_t& r3,
                                        uint32_t addr)
{
    asm volatile("ldmatrix.sync.aligned.m8n8.x4.shared.b16 {%0,%1,%2,%3}, [%4];"
                 : "=r"(r0), "=r"(r1), "=r"(r2), "=r"(r3) : "r"(addr));
}
__device__ __forceinline__ void ldsm_x2_t(uint32_t& r0, uint32_t& r1, uint32_t addr)
{
    asm volatile("ldmatrix.sync.aligned.m8n8.x2.trans.shared.b16 {%0,%1}, [%2];"
                 : "=r"(r0), "=r"(r1) : "r"(addr));
}

__device__ __forceinline__ void cp16s(uint32_t s, const void* g) {
    asm volatile("cp.async.ca.shared.global [%0], [%1], 16;\n" :: "r"(s), "l"(g));
}
__device__ __forceinline__ void cp_commit() { asm volatile("cp.async.commit_group;\n"); }
template<int N>
__device__ __forceinline__ void cp_wait() { asm volatile("cp.async.wait_group %0;\n" :: "n"(N)); }

// ---------------- pack weights to fp16 ----------------
__global__ void pack_kernel(const float* __restrict__ wq, const float* __restrict__ bq,
                            const float* __restrict__ wk, const float* __restrict__ bk,
                            const float* __restrict__ wv, const float* __restrict__ bv,
                            const float* __restrict__ wo)
{
    int idx = blockIdx.x * blockDim.x + threadIdx.x;
    if (idx < YM * CC) {
        int r = idx / CC, c = idx % CC;
        float v;
        if (r < CS)           v = wq[r * CC + c];
        else if (r < 2 * CS)  v = wk[(r - CS) * CC + c];
        else if (r < M1)      v = wv[(r - 2 * CS) * CC + c];
        else                  v = 0.0f;
        g_Wh[idx] = __float2half(v);
    }
    if (idx < CC * CC) g_Woh[idx] = __float2half(wo[idx]);
    if (idx < YM) {
        float v;
        if (idx < CS)          v = bq[idx];
        else if (idx < 2 * CS) v = bk[idx - CS];
        else if (idx < M1)     v = bv[idx - 2 * CS];
        else                   v = 0.0f;
        g_bias[idx] = v;
    }
}

// ---------------- x -> fp16 ----------------
__global__ void cvtx_kernel(const float* __restrict__ x)
{
    long i = ((long)blockIdx.x * blockDim.x + threadIdx.x) * 8;
    const long total = (long)BB * CC * HW;
    if (i >= total) return;
    float4 v0 = *(const float4*)(x + i);
    float4 v1 = *(const float4*)(x + i + 4);
    union { __half2 h[4]; uint4 u; } U;
    U.h[0] = __floats2half2_rn(v0.x, v0.y);
    U.h[1] = __floats2half2_rn(v0.z, v0.w);
    U.h[2] = __floats2half2_rn(v1.x, v1.y);
    U.h[3] = __floats2half2_rn(v1.z, v1.w);
    *(uint4*)(g_Xh + i) = U.u;
}

// ---------------- fp16 tensor-core GEMM, 3-stage cp.async + ldmatrix ----------------
#define AST 40        // A smem row stride (halfs)
#define BST 136       // B smem row stride (halfs)
#define A_STG (128 * AST)
#define B_STG (32 * BST)
#define H_SMEM (3 * (A_STG + B_STG) * 2)

template<bool HAS_BIAS, bool HAS_RES, bool OUT_HALF>
__global__ __launch_bounds__(256, 2)
void hgemm(int M, int N, int K,
           const __half* __restrict__ A, long sA,
           const __half* __restrict__ Bm, long sB,
           void* __restrict__ Cm, long sC,
           const float* __restrict__ bias,
           const float* __restrict__ res, long sR,
           const float* __restrict__ gamma_ptr)
{
    extern __shared__ __half hsm[];
    uint32_t s0 = (uint32_t)__cvta_generic_to_shared(hsm);

    int b = blockIdx.z;
    const __half* Ab = A  + (long)b * sA;
    const __half* Bb = Bm + (long)b * sB;

    int m0 = blockIdx.y * 128;
    int n0 = blockIdx.x * 128;
    int t    = threadIdx.x;
    int warp = t >> 5;
    int lane = t & 31;
    int warpM = warp >> 2;
    int warpN = warp & 3;
    int grp = lane >> 2;
    int tig = lane & 3;

    int ar0 = t >> 2,  ac0 = (t & 3) * 8;
    int ar1 = ar0 + 64;
    int br0 = t >> 4,  bc0 = (t & 15) * 8;
    int br1 = br0 + 16;

    uint32_t aLane = (uint32_t)(((warpM * 64 + (lane & 15)) * AST + (lane >> 4) * 8) * 2);
    uint32_t bLane = (uint32_t)(((lane & 15) * BST + warpN * 32) * 2);

    float acc[4][4][4];
#pragma unroll
    for (int i = 0; i < 4; i++)
#pragma unroll
        for (int j = 0; j < 4; j++)
#pragma unroll
            for (int f = 0; f < 4; f++) acc[i][j][f] = 0.f;

    const int T = K / 32;

    auto load_tile = [&](int ti) {
        int s = ti % 3;
        int k0 = ti * 32;
        uint32_t ab = s0 + (uint32_t)(s * (A_STG + B_STG) * 2);
        uint32_t bb = ab + A_STG * 2;
        cp16s(ab + (ar0 * AST + ac0) * 2, Ab + (long)(m0 + ar0) * K + k0 + ac0);
        cp16s(ab + (ar1 * AST + ac0) * 2, Ab + (long)(m0 + ar1) * K + k0 + ac0);
        cp16s(bb + (br0 * BST + bc0) * 2, Bb + (long)(k0 + br0) * N + n0 + bc0);
        cp16s(bb + (br1 * BST + bc0) * 2, Bb + (long)(k0 + br1) * N + n0 + bc0);
        cp_commit();
    };

    load_tile(0);
    load_tile(1);

    for (int ti = 0; ti < T; ti++) {
        if (ti + 2 < T) load_tile(ti + 2);
        else            cp_commit();
        cp_wait<2>();
        __syncthreads();

        int s = ti % 3;
        uint32_t ab = s0 + (uint32_t)(s * (A_STG + B_STG) * 2);
        uint32_t aBase = ab + aLane;
        uint32_t bBase = ab + A_STG * 2 + bLane;

#pragma unroll
        for (int kb = 0; kb < 32; kb += 16) {
            uint32_t af[4][4], bf[4][2];
#pragma unroll
            for (int mt = 0; mt < 4; mt++)
                ldsm_x4(af[mt][0], af[mt][1], af[mt][2], af[mt][3],
                        aBase + (uint32_t)((mt * 16 * AST + kb) * 2));
#pragma unroll
            for (int nt = 0; nt < 4; nt++)
                ldsm_x2_t(bf[nt][0], bf[nt][1],
                          bBase + (uint32_t)((kb * BST + nt * 8) * 2));
#pragma unroll
            for (int mt = 0; mt < 4; mt++)
#pragma unroll
                for (int nt = 0; nt < 4; nt++)
                    mma_f16(acc[mt][nt][0], acc[mt][nt][1], acc[mt][nt][2], acc[mt][nt][3],
                            af[mt][0], af[mt][1], af[mt][2], af[mt][3],
                            bf[nt][0], bf[nt][1]);
        }
        __syncthreads();
    }

    float gm = 1.0f;
    if (HAS_RES) gm = *gamma_ptr;
    const float* resb = HAS_RES ? (res + (long)b * sR) : nullptr;

#pragma unroll
    for (int mt = 0; mt < 4; mt++) {
        int row0 = m0 + warpM * 64 + mt * 16 + grp;
        int row1 = row0 + 8;
        float bv0 = HAS_BIAS ? bias[row0] : 0.0f;
        float bv1 = HAS_BIAS ? bias[row1] : 0.0f;
#pragma unroll
        for (int nt = 0; nt < 4; nt++) {
            int col = n0 + warpN * 32 + nt * 8 + 2 * tig;
            long off0 = (long)row0 * N + col;
            long off1 = (long)row1 * N + col;
            float2 o0, o1;
            o0.x = acc[mt][nt][0] + bv0; o0.y = acc[mt][nt][1] + bv0;
            o1.x = acc[mt][nt][2] + bv1; o1.y = acc[mt][nt][3] + bv1;
            if (HAS_RES) {
                float2 r0 = *(const float2*)(resb + off0);
                float2 r1 = *(const float2*)(resb + off1);
                o0.x = gm * o0.x + r0.x;  o0.y = gm * o0.y + r0.y;
                o1.x = gm * o1.x + r1.x;  o1.y = gm * o1.y + r1.y;
            }
            if (OUT_HALF) {
                __half* Ch = (__half*)Cm + (long)b * sC;
                *(__half2*)(Ch + off0) = __floats2half2_rn(o0.x, o0.y);
                *(__half2*)(Ch + off1) = __floats2half2_rn(o1.x, o1.y);
            } else {
                float* Cf = (float*)Cm + (long)b * sC;
                *(float2*)(Cf + off0) = o0;
                *(float2*)(Cf + off1) = o1;
            }
        }
    }
}

// ---------------- maxpool Q -> transposed fp16 [b][n][c] ----------------
__global__ void poolQ_kernel()
{
    long idx = (long)blockIdx.x * blockDim.x + threadIdx.x;
    const long total = (long)BB * CS * NP;
    if (idx >= total) return;
    int np = (int)(idx & (NP - 1));
    int c  = (int)((idx >> 10) % CS);
    int b  = (int)(idx / ((long)CS * NP));
    int hp = np >> 5, wp = np & 31;
    const __half* src = g_Yh + ((long)b * YM + c) * HW + (hp * 2) * 64 + wp * 2;
    float m = fmaxf(fmaxf(__half2float(src[0]),  __half2float(src[1])),
                    fmaxf(__half2float(src[64]), __half2float(src[65])));
    g_Qt[((long)b * NP + np) * CS + c] = __float2half(m);
}

// ---------------- maxpool V * invsum -> fp16 ----------------
__global__ void poolV_kernel()
{
    long idx = (long)blockIdx.x * blockDim.x + threadIdx.x;
    const long total = (long)BB * CC * NP;
    if (idx >= total) return;
    int np = (int)(idx & (NP - 1));
    int c  = (int)((idx >> 10) % CC);
    int b  = (int)(idx / ((long)CC * NP));
    int hp = np >> 5, wp = np & 31;
    const __half* src = g_Yh + ((long)b * YM + 2 * CS + c) * HW + (hp * 2) * 64 + wp * 2;
    float m = fmaxf(fmaxf(__half2float(src[0]),  __half2float(src[1])),
                    fmaxf(__half2float(src[64]), __half2float(src[65])));
    g_Vph[((long)b * CC + c) * NP + np] = __float2half(m * g_invsum[(long)b * NP + np]);
}

// ---------------- E = Qt @ K via fp16 MMA; pass A: rowmax, pass B: exp+sum+store ----------------
// M-tile = 128 n-rows, loop 32 chunks of 128 m-cols, K-dim = 32 (2 MMA k-steps, A resident).
#define QST 40
#define KST 136

template<bool DO_EXP>
__global__ __launch_bounds__(256) void energyE_kernel()
{
    __shared__ __half Qs[128 * QST];
    __shared__ __half Ks[2][32 * KST];
    __shared__ float  Red[128][4];

    int b  = blockIdx.y;
    int n0 = blockIdx.x * 128;
    const __half* Qb = g_Qt + ((long)b * NP + n0) * CS;
    const __half* Kb = g_Yh + ((long)b * YM + CS) * HW;

    int t = threadIdx.x;
    int lane = t & 31;
    int warp = t >> 5;
    int warpM = warp >> 2, warpN = warp & 3;
    int grp = lane >> 2, tig = lane & 3;

    uint32_t sQ  = (uint32_t)__cvta_generic_to_shared(Qs);
    uint32_t sK0 = (uint32_t)__cvta_generic_to_shared(&Ks[0][0]);
    uint32_t sK1 = (uint32_t)__cvta_generic_to_shared(&Ks[1][0]);

    // load Q tile (128 x 32 halfs): 512 chunks of 16B
#pragma unroll
    for (int i = 0; i < 2; i++) {
        int idx = t + 256 * i;
        int r = idx >> 2, c8 = (idx & 3) * 8;
        cp16s(sQ + (r * QST + c8) * 2, Qb + (long)r * CS + c8);
    }
    auto loadK = [&](int ch, int buf) {
        uint32_t base = buf ? sK1 : sK0;
#pragma unroll
        for (int i = 0; i < 2; i++) {
            int idx = t + 256 * i;
            int c = idx >> 4, m8 = (idx & 15) * 8;
            cp16s(base + (c * KST + m8) * 2, Kb + (long)c * HW + ch * 128 + m8);
        }
        cp_commit();
    };
    loadK(0, 0);   // group 0 = Q + K chunk 0
    loadK(1, 1);   // group 1 = K chunk 1

    cp_wait<1>();   // group 0 resident (Q + K0)
    __syncthreads();

    // A fragments (load once): k 0..15 and 16..31
    uint32_t aBase = sQ + (uint32_t)(((warpM * 64 + (lane & 15)) * QST + (lane >> 4) * 8) * 2);
    uint32_t af[4][4], af2[4][4];
#pragma unroll
    for (int mt = 0; mt < 4; mt++) {
        ldsm_x4(af[mt][0],  af[mt][1],  af[mt][2],  af[mt][3],
                aBase + (uint32_t)((mt * 16 * QST) * 2));
        ldsm_x4(af2[mt][0], af2[mt][1], af2[mt][2], af2[mt][3],
                aBase + (uint32_t)((mt * 16 * QST + 16) * 2));
    }

    float mrow[4][2];
    if (DO_EXP) {
#pragma unroll
        for (int mt = 0; mt < 4; mt++) {
            int r0 = warpM * 64 + mt * 16 + grp;
            mrow[mt][0] = g_M[(long)b * NP + n0 + r0];
            mrow[mt][1] = g_M[(long)b * NP + n0 + r0 + 8];
        }
    }

    float red[4][2];
#pragma unroll
    for (int mt = 0; mt < 4; mt++) {
        red[mt][0] = DO_EXP ? 0.f : -1e30f;
        red[mt][1] = DO_EXP ? 0.f : -1e30f;
    }

    __half* Pb = DO_EXP ? (g_Ph + (long)b * NP * HW + (long)n0 * HW) : nullptr;
    uint32_t bLane = (uint32_t)(((lane & 15) * KST + warpN * 32) * 2);

    // pipeline: chunk ch lives in buffer ch&1; refilled with chunk ch+2 after consumption.
    for (int ch = 0; ch < 32; ch++) {
        int buf = ch & 1;
        cp_wait<1>();          // chunk ch's group complete (all but most recent commit)
        __syncthreads();

        uint32_t bBase = (buf ? sK1 : sK0) + bLane;

#pragma unroll
        for (int nt = 0; nt < 4; nt++) {
            float acc[4][4];
#pragma unroll
            for (int mt = 0; mt < 4; mt++)
#pragma unroll
                for (int f = 0; f < 4; f++) acc[mt][f] = 0.f;

            uint32_t bf0[2], bf1[2];
            ldsm_x2_t(bf0[0], bf0[1], bBase + (uint32_t)((nt * 8) * 2));
            ldsm_x2_t(bf1[0], bf1[1], bBase + (uint32_t)((16 * KST + nt * 8) * 2));
#pragma unroll
            for (int mt = 0; mt < 4; mt++) {
                mma_f16(acc[mt][0], acc[mt][1], acc[mt][2], acc[mt][3],
                        af[mt][0],  af[mt][1],  af[mt][2],  af[mt][3],  bf0[0], bf0[1]);
                mma_f16(acc[mt][0], acc[mt][1], acc[mt][2], acc[mt][3],
                        af2[mt][0], af2[mt][1], af2[mt][2], af2[mt][3], bf1[0], bf1[1]);
            }

            if (DO_EXP) {
#pragma unroll
                for (int mt = 0; mt < 4; mt++) {
                    float p0 = __expf(acc[mt][0] - mrow[mt][0]);
                    float p1 = __expf(acc[mt][1] - mrow[mt][0]);
                    float p2 = __expf(acc[mt][2] - mrow[mt][1]);
                    float p3 = __expf(acc[mt][3] - mrow[mt][1]);
                    red[mt][0] += p0 + p1;
                    red[mt][1] += p2 + p3;
                    int r0 = warpM * 64 + mt * 16 + grp;
                    int col = ch * 128 + warpN * 32 + nt * 8 + 2 * tig;
                    *(__half2*)(Pb + (long)r0 * HW + col)       = __floats2half2_rn(p0, p1);
                    *(__half2*)(Pb + (long)(r0 + 8) * HW + col) = __floats2half2_rn(p2, p3);
                }
            } else {
#pragma unroll
                for (int mt = 0; mt < 4; mt++) {
                    red[mt][0] = fmaxf(red[mt][0], fmaxf(acc[mt][0], acc[mt][1]));
                    red[mt][1] = fmaxf(red[mt][1], fmaxf(acc[mt][2], acc[mt][3]));
                }
            }
        }
        __syncthreads();           // all warps done with buf before refill
        if (ch + 2 < 32) loadK(ch + 2, buf);
        else             cp_commit();       // keep group cadence
    }

    // cross-lane (tig) reduce, then cross-warpN via smem
#pragma unroll
    for (int mt = 0; mt < 4; mt++)
#pragma unroll
        for (int h = 0; h < 2; h++) {
            float v = red[mt][h];
            if (DO_EXP) {
                v += __shfl_xor_sync(0xffffffffu, v, 1);
                v += __shfl_xor_sync(0xffffffffu, v, 2);
            } else {
                v = fmaxf(v, __shfl_xor_sync(0xffffffffu, v, 1));
                v = fmaxf(v, __shfl_xor_sync(0xffffffffu, v, 2));
            }
            if (tig == 0) {
                int row = warpM * 64 + mt * 16 + grp + h * 8;
                Red[row][warpN] = v;
            }
        }
    __syncthreads();
    if (t < 128) {
        if (DO_EXP) {
            float s = Red[t][0] + Red[t][1] + Red[t][2] + Red[t][3];
            g_invsum[(long)b * NP + n0 + t] = 1.0f / s;
        } else {
            float v = fmaxf(fmaxf(Red[t][0], Red[t][1]), fmaxf(Red[t][2], Red[t][3]));
            g_M[(long)b * NP + n0 + t] = v;
        }
    }
}

// ---------------- launch ----------------
extern "C" void kernel_launch(void* const* d_in, const int* in_sizes, int n_in,
                              void* d_out, int out_size)
{
    const float* x     = (const float*)d_in[0];
    const float* wq    = (const float*)d_in[1];
    const float* bq    = (const float*)d_in[2];
    const float* wk    = (const float*)d_in[3];
    const float* bk    = (const float*)d_in[4];
    const float* wv    = (const float*)d_in[5];
    const float* bv    = (const float*)d_in[6];
    const float* wo    = (const float*)d_in[7];
    const float* bo    = (const float*)d_in[8];
    const float* gamma = (const float*)d_in[9];
    float* out = (float*)d_out;

    __half *pWh, *pWoh, *pXh, *pYh, *pPh, *pVph, *pOut1h;
    float *pBias;
    cudaGetSymbolAddress((void**)&pWh,    g_Wh);
    cudaGetSymbolAddress((void**)&pBias,  g_bias);
    cudaGetSymbolAddress((void**)&pWoh,   g_Woh);
    cudaGetSymbolAddress((void**)&pXh,    g_Xh);
    cudaGetSymbolAddress((void**)&pYh,    g_Yh);
    cudaGetSymbolAddress((void**)&pPh,    g_Ph);
    cudaGetSymbolAddress((void**)&pVph,   g_Vph);
    cudaGetSymbolAddress((void**)&pOut1h, g_out1h);

    cudaFuncSetAttribute(hgemm<true,  false, true >, cudaFuncAttributeMaxDynamicSharedMemorySize, H_SMEM);
    cudaFuncSetAttribute(hgemm<false, false, true >, cudaFuncAttributeMaxDynamicSharedMemorySize, H_SMEM);
    cudaFuncSetAttribute(hgemm<true,  true,  false>, cudaFuncAttributeMaxDynamicSharedMemorySize, H_SMEM);

    // 1. pack weights; convert x
    pack_kernel<<<(YM * CC + 255) / 256, 256>>>(wq, bq, wk, bk, wv, bv, wo);
    {
        long total8 = (long)BB * CC * HW / 8;
        cvtx_kernel<<<(int)((total8 + 255) / 256), 256>>>(x);
    }

    // 2. QKV conv -> Yh fp16
    {
        dim3 grid(HW / 128, YM / 128, BB);
        hgemm<true, false, true><<<grid, 256, H_SMEM>>>(
            YM, HW, CC,
            pWh, 0L,
            pXh, (long)CC * HW,
            pYh, (long)YM * HW,
            pBias, nullptr, 0L, nullptr);
    }

    // 3. pool Q (transposed fp16)
    {
        long total = (long)BB * CS * NP;
        poolQ_kernel<<<(int)((total + 255) / 256), 256>>>();
    }

    // 4. rowmax of E (fp16 MMA)
    {
        dim3 grid(NP / 128, BB);
        energyE_kernel<false><<<grid, 256>>>();
    }

    // 5. P = exp(E - M) fp16 + invsum (fp16 MMA)
    {
        dim3 grid(NP / 128, BB);
        energyE_kernel<true><<<grid, 256>>>();
    }

    // 6. pool V with invsum folding -> fp16
    {
        long total = (long)BB * CC * NP;
        poolV_kernel<<<(int)((total + 255) / 256), 256>>>();
    }

    // 7. out1 = Vph @ Ph (fp16 out)
    {
        dim3 grid(HW / 128, CC / 128, BB);
        hgemm<false, false, true><<<grid, 256, H_SMEM>>>(
            CC, HW, NP,
            pVph, (long)CC * NP,
            pPh, (long)NP * HW,
            pOut1h, (long)CC * HW,
            nullptr, nullptr, 0L, nullptr);
    }

    // 8. out = gamma * (Woh @ out1h + bo) + x
    {
        dim3 grid(HW / 128, CC / 128, BB);
        hgemm<true, true, false><<<grid, 256, H_SMEM>>>(
            CC, HW, CC,
            pWoh, 0L,
            pOut1h, (long)CC * HW,
            out, (long)CC * HW,
            bo,
            x, (long)CC * HW,
            gamma);
    }
}

// round 16
// speedup vs baseline: 2.3672x; 1.0239x over previous
#include <cuda_runtime.h>
#include <cuda_fp16.h>
#include <math.h>
#include <stdint.h>

// Problem constants
#define BB   16
#define CC   256
#define HW   4096     // 64*64
#define CS   32
#define NP   1024     // 32*32
#define M1   320      // CS + CS + CC
#define YM   384      // M1 padded to multiple of 128

// ---------------- device scratch ----------------
__device__ __half g_Wh[YM * CC];                 // packed [wq;wk;wv;0] fp16
__device__ float  g_bias[YM];
__device__ __half g_Woh[CC * CC];                // wo fp16
__device__ __half g_Xh[(long)BB * CC * HW];      // x fp16
__device__ __half g_Yh[(long)BB * YM * HW];      // QKV conv outputs fp16
__device__ __half g_Qt[(long)BB * NP * CS];      // pooled Q, transposed [b][n][c] fp16
__device__ float  g_M[(long)BB * NP];            // per-row max of E
__device__ float  g_invsum[(long)BB * NP];       // exp(M)/sum(exp(E))
__device__ __half g_Vph[(long)BB * CC * NP];     // pooled V * invsum fp16
__device__ __half g_out1h[(long)BB * CC * HW];   // V' @ softmax fp16

// ---------------- PTX helpers ----------------
__device__ __forceinline__ void mma_f16(float& c0, float& c1, float& c2, float& c3,
                                        uint32_t a0, uint32_t a1, uint32_t a2, uint32_t a3,
                                        uint32_t b0, uint32_t b1)
{
    asm volatile(
        "mma.sync.aligned.m16n8k16.row.col.f32.f16.f16.f32 "
        "{%0,%1,%2,%3}, {%4,%5,%6,%7}, {%8,%9}, {%0,%1,%2,%3};\n"
        : "+f"(c0), "+f"(c1), "+f"(c2), "+f"(c3)
        : "r"(a0), "r"(a1), "r"(a2), "r"(a3), "r"(b0), "r"(b1));
}

__device__ __forceinline__ void ldsm_x4(uint32_t& r0, uint32_t& r1, uint32_t& r2, uint32_t& r3,
                                        uint32_t addr)
{
    asm volatile("ldmatrix.sync.aligned.m8n8.x4.shared.b16 {%0,%1,%2,%3}, [%4];"
                 : "=r"(r0), "=r"(r1), "=r"(r2), "=r"(r3) : "r"(addr));
}
__device__ __forceinline__ void ldsm_x2_t(uint32_t& r0, uint32_t& r1, uint32_t addr)
{
    asm volatile("ldmatrix.sync.aligned.m8n8.x2.trans.shared.b16 {%0,%1}, [%2];"
                 : "=r"(r0), "=r"(r1) : "r"(addr));
}

__device__ __forceinline__ void cp16s(uint32_t s, const void* g) {
    asm volatile("cp.async.ca.shared.global [%0], [%1], 16;\n" :: "r"(s), "l"(g));
}
__device__ __forceinline__ void cp_commit() { asm volatile("cp.async.commit_group;\n"); }
template<int N>
__device__ __forceinline__ void cp_wait() { asm volatile("cp.async.wait_group %0;\n" :: "n"(N)); }

// ---------------- pack weights to fp16 ----------------
__global__ void pack_kernel(const float* __restrict__ wq, const float* __restrict__ bq,
                            const float* __restrict__ wk, const float* __restrict__ bk,
                            const float* __restrict__ wv, const float* __restrict__ bv,
                            const float* __restrict__ wo)
{
    int idx = blockIdx.x * blockDim.x + threadIdx.x;
    if (idx < YM * CC) {
        int r = idx / CC, c = idx % CC;
        float v;
        if (r < CS)           v = wq[r * CC + c];
        else if (r < 2 * CS)  v = wk[(r - CS) * CC + c];
        else if (r < M1)      v = wv[(r - 2 * CS) * CC + c];
        else                  v = 0.0f;
        g_Wh[idx] = __float2half(v);
    }
    if (idx < CC * CC) g_Woh[idx] = __float2half(wo[idx]);
    if (idx < YM) {
        float v;
        if (idx < CS)          v = bq[idx];
        else if (idx < 2 * CS) v = bk[idx - CS];
        else if (idx < M1)     v = bv[idx - 2 * CS];
        else                   v = 0.0f;
        g_bias[idx] = v;
    }
}

// ---------------- x -> fp16 ----------------
__global__ void cvtx_kernel(const float* __restrict__ x)
{
    long i = ((long)blockIdx.x * blockDim.x + threadIdx.x) * 8;
    const long total = (long)BB * CC * HW;
    if (i >= total) return;
    float4 v0 = *(const float4*)(x + i);
    float4 v1 = *(const float4*)(x + i + 4);
    union { __half2 h[4]; uint4 u; } U;
    U.h[0] = __floats2half2_rn(v0.x, v0.y);
    U.h[1] = __floats2half2_rn(v0.z, v0.w);
    U.h[2] = __floats2half2_rn(v1.x, v1.y);
    U.h[3] = __floats2half2_rn(v1.z, v1.w);
    *(uint4*)(g_Xh + i) = U.u;
}

// ---------------- fp16 tensor-core GEMM, 3-stage cp.async + ldmatrix ----------------
#define AST 40
#define BST 136
#define A_STG (128 * AST)
#define B_STG (32 * BST)
#define H_SMEM (3 * (A_STG + B_STG) * 2)

template<bool HAS_BIAS, bool HAS_RES, bool OUT_HALF>
__global__ __launch_bounds__(256, 2)
void hgemm(int M, int N, int K,
           const __half* __restrict__ A, long sA,
           const __half* __restrict__ Bm, long sB,
           void* __restrict__ Cm, long sC,
           const float* __restrict__ bias,
           const float* __restrict__ res, long sR,
           const float* __restrict__ gamma_ptr)
{
    extern __shared__ __half hsm[];
    uint32_t s0 = (uint32_t)__cvta_generic_to_shared(hsm);

    int b = blockIdx.z;
    const __half* Ab = A  + (long)b * sA;
    const __half* Bb = Bm + (long)b * sB;

    int m0 = blockIdx.y * 128;
    int n0 = blockIdx.x * 128;
    int t    = threadIdx.x;
    int warp = t >> 5;
    int lane = t & 31;
    int warpM = warp >> 2;
    int warpN = warp & 3;
    int grp = lane >> 2;
    int tig = lane & 3;

    int ar0 = t >> 2,  ac0 = (t & 3) * 8;
    int ar1 = ar0 + 64;
    int br0 = t >> 4,  bc0 = (t & 15) * 8;
    int br1 = br0 + 16;

    uint32_t aLane = (uint32_t)(((warpM * 64 + (lane & 15)) * AST + (lane >> 4) * 8) * 2);
    uint32_t bLane = (uint32_t)(((lane & 15) * BST + warpN * 32) * 2);

    float acc[4][4][4];
#pragma unroll
    for (int i = 0; i < 4; i++)
#pragma unroll
        for (int j = 0; j < 4; j++)
#pragma unroll
            for (int f = 0; f < 4; f++) acc[i][j][f] = 0.f;

    const int T = K / 32;

    auto load_tile = [&](int ti) {
        int s = ti % 3;
        int k0 = ti * 32;
        uint32_t ab = s0 + (uint32_t)(s * (A_STG + B_STG) * 2);
        uint32_t bb = ab + A_STG * 2;
        cp16s(ab + (ar0 * AST + ac0) * 2, Ab + (long)(m0 + ar0) * K + k0 + ac0);
        cp16s(ab + (ar1 * AST + ac0) * 2, Ab + (long)(m0 + ar1) * K + k0 + ac0);
        cp16s(bb + (br0 * BST + bc0) * 2, Bb + (long)(k0 + br0) * N + n0 + bc0);
        cp16s(bb + (br1 * BST + bc0) * 2, Bb + (long)(k0 + br1) * N + n0 + bc0);
        cp_commit();
    };

    load_tile(0);
    load_tile(1);

    for (int ti = 0; ti < T; ti++) {
        if (ti + 2 < T) load_tile(ti + 2);
        else            cp_commit();
        cp_wait<2>();
        __syncthreads();

        int s = ti % 3;
        uint32_t ab = s0 + (uint32_t)(s * (A_STG + B_STG) * 2);
        uint32_t aBase = ab + aLane;
        uint32_t bBase = ab + A_STG * 2 + bLane;

#pragma unroll
        for (int kb = 0; kb < 32; kb += 16) {
            uint32_t af[4][4], bf[4][2];
#pragma unroll
            for (int mt = 0; mt < 4; mt++)
                ldsm_x4(af[mt][0], af[mt][1], af[mt][2], af[mt][3],
                        aBase + (uint32_t)((mt * 16 * AST + kb) * 2));
#pragma unroll
            for (int nt = 0; nt < 4; nt++)
                ldsm_x2_t(bf[nt][0], bf[nt][1],
                          bBase + (uint32_t)((kb * BST + nt * 8) * 2));
#pragma unroll
            for (int mt = 0; mt < 4; mt++)
#pragma unroll
                for (int nt = 0; nt < 4; nt++)
                    mma_f16(acc[mt][nt][0], acc[mt][nt][1], acc[mt][nt][2], acc[mt][nt][3],
                            af[mt][0], af[mt][1], af[mt][2], af[mt][3],
                            bf[nt][0], bf[nt][1]);
        }
        __syncthreads();
    }

    float gm = 1.0f;
    if (HAS_RES) gm = *gamma_ptr;
    const float* resb = HAS_RES ? (res + (long)b * sR) : nullptr;

#pragma unroll
    for (int mt = 0; mt < 4; mt++) {
        int row0 = m0 + warpM * 64 + mt * 16 + grp;
        int row1 = row0 + 8;
        float bv0 = HAS_BIAS ? bias[row0] : 0.0f;
        float bv1 = HAS_BIAS ? bias[row1] : 0.0f;
#pragma unroll
        for (int nt = 0; nt < 4; nt++) {
            int col = n0 + warpN * 32 + nt * 8 + 2 * tig;
            long off0 = (long)row0 * N + col;
            long off1 = (long)row1 * N + col;
            float2 o0, o1;
            o0.x = acc[mt][nt][0] + bv0; o0.y = acc[mt][nt][1] + bv0;
            o1.x = acc[mt][nt][2] + bv1; o1.y = acc[mt][nt][3] + bv1;
            if (HAS_RES) {
                float2 r0 = *(const float2*)(resb + off0);
                float2 r1 = *(const float2*)(resb + off1);
                o0.x = gm * o0.x + r0.x;  o0.y = gm * o0.y + r0.y;
                o1.x = gm * o1.x + r1.x;  o1.y = gm * o1.y + r1.y;
            }
            if (OUT_HALF) {
                __half* Ch = (__half*)Cm + (long)b * sC;
                *(__half2*)(Ch + off0) = __floats2half2_rn(o0.x, o0.y);
                *(__half2*)(Ch + off1) = __floats2half2_rn(o1.x, o1.y);
            } else {
                float* Cf = (float*)Cm + (long)b * sC;
                *(float2*)(Cf + off0) = o0;
                *(float2*)(Cf + off1) = o1;
            }
        }
    }
}

// ---------------- maxpool Q -> transposed fp16 [b][n][c] ----------------
__global__ void poolQ_kernel()
{
    long idx = (long)blockIdx.x * blockDim.x + threadIdx.x;
    const long total = (long)BB * CS * NP;
    if (idx >= total) return;
    int np = (int)(idx & (NP - 1));
    int c  = (int)((idx >> 10) % CS);
    int b  = (int)(idx / ((long)CS * NP));
    int hp = np >> 5, wp = np & 31;
    const __half* src = g_Yh + ((long)b * YM + c) * HW + (hp * 2) * 64 + wp * 2;
    float m = fmaxf(fmaxf(__half2float(src[0]),  __half2float(src[1])),
                    fmaxf(__half2float(src[64]), __half2float(src[65])));
    g_Qt[((long)b * NP + np) * CS + c] = __float2half(m);
}

// ---------------- maxpool V * invsum -> fp16 ----------------
__global__ void poolV_kernel()
{
    long idx = (long)blockIdx.x * blockDim.x + threadIdx.x;
    const long total = (long)BB * CC * NP;
    if (idx >= total) return;
    int np = (int)(idx & (NP - 1));
    int c  = (int)((idx >> 10) % CC);
    int b  = (int)(idx / ((long)CC * NP));
    int hp = np >> 5, wp = np & 31;
    const __half* src = g_Yh + ((long)b * YM + 2 * CS + c) * HW + (hp * 2) * 64 + wp * 2;
    float m = fmaxf(fmaxf(__half2float(src[0]),  __half2float(src[1])),
                    fmaxf(__half2float(src[64]), __half2float(src[65])));
    g_Vph[((long)b * CC + c) * NP + np] = __float2half(m * g_invsum[(long)b * NP + np]);
}

// ---------------- maxsumE: single pass, rowmax AND sum(exp(E)), no P store ----------------
#define QST 40
#define KST 136

__global__ __launch_bounds__(256) void maxsumE_kernel()
{
    __shared__ __half Qs[128 * QST];
    __shared__ __half Ks[2][32 * KST];
    __shared__ float  RedM[128][4];
    __shared__ float  RedS[128][4];

    int b  = blockIdx.y;
    int n0 = blockIdx.x * 128;
    const __half* Qb = g_Qt + ((long)b * NP + n0) * CS;
    const __half* Kb = g_Yh + ((long)b * YM + CS) * HW;

    int t = threadIdx.x;
    int lane = t & 31;
    int warp = t >> 5;
    int warpM = warp >> 2, warpN = warp & 3;
    int grp = lane >> 2, tig = lane & 3;

    uint32_t sQ  = (uint32_t)__cvta_generic_to_shared(Qs);
    uint32_t sK0 = (uint32_t)__cvta_generic_to_shared(&Ks[0][0]);
    uint32_t sK1 = (uint32_t)__cvta_generic_to_shared(&Ks[1][0]);

#pragma unroll
    for (int i = 0; i < 2; i++) {
        int idx = t + 256 * i;
        int r = idx >> 2, c8 = (idx & 3) * 8;
        cp16s(sQ + (r * QST + c8) * 2, Qb + (long)r * CS + c8);
    }
    auto loadK = [&](int ch, int buf) {
        uint32_t base = buf ? sK1 : sK0;
#pragma unroll
        for (int i = 0; i < 2; i++) {
            int idx = t + 256 * i;
            int c = idx >> 4, m8 = (idx & 15) * 8;
            cp16s(base + (c * KST + m8) * 2, Kb + (long)c * HW + ch * 128 + m8);
        }
        cp_commit();
    };
    loadK(0, 0);
    loadK(1, 1);

    cp_wait<1>();
    __syncthreads();

    uint32_t aBase = sQ + (uint32_t)(((warpM * 64 + (lane & 15)) * QST + (lane >> 4) * 8) * 2);
    uint32_t af[4][4], af2[4][4];
#pragma unroll
    for (int mt = 0; mt < 4; mt++) {
        ldsm_x4(af[mt][0],  af[mt][1],  af[mt][2],  af[mt][3],
                aBase + (uint32_t)((mt * 16 * QST) * 2));
        ldsm_x4(af2[mt][0], af2[mt][1], af2[mt][2], af2[mt][3],
                aBase + (uint32_t)((mt * 16 * QST + 16) * 2));
    }

    float rmx[4][2], rsm[4][2];
#pragma unroll
    for (int mt = 0; mt < 4; mt++) {
        rmx[mt][0] = -1e30f; rmx[mt][1] = -1e30f;
        rsm[mt][0] = 0.f;    rsm[mt][1] = 0.f;
    }

    uint32_t bLane = (uint32_t)(((lane & 15) * KST + warpN * 32) * 2);

    for (int ch = 0; ch < 32; ch++) {
        int buf = ch & 1;
        cp_wait<1>();
        __syncthreads();

        uint32_t bBase = (buf ? sK1 : sK0) + bLane;

#pragma unroll
        for (int nt = 0; nt < 4; nt++) {
            float acc[4][4];
#pragma unroll
            for (int mt = 0; mt < 4; mt++)
#pragma unroll
                for (int f = 0; f < 4; f++) acc[mt][f] = 0.f;

            uint32_t bf0[2], bf1[2];
            ldsm_x2_t(bf0[0], bf0[1], bBase + (uint32_t)((nt * 8) * 2));
            ldsm_x2_t(bf1[0], bf1[1], bBase + (uint32_t)((16 * KST + nt * 8) * 2));
#pragma unroll
            for (int mt = 0; mt < 4; mt++) {
                mma_f16(acc[mt][0], acc[mt][1], acc[mt][2], acc[mt][3],
                        af[mt][0],  af[mt][1],  af[mt][2],  af[mt][3],  bf0[0], bf0[1]);
                mma_f16(acc[mt][0], acc[mt][1], acc[mt][2], acc[mt][3],
                        af2[mt][0], af2[mt][1], af2[mt][2], af2[mt][3], bf1[0], bf1[1]);
            }
#pragma unroll
            for (int mt = 0; mt < 4; mt++) {
                rmx[mt][0] = fmaxf(rmx[mt][0], fmaxf(acc[mt][0], acc[mt][1]));
                rmx[mt][1] = fmaxf(rmx[mt][1], fmaxf(acc[mt][2], acc[mt][3]));
                rsm[mt][0] += __expf(acc[mt][0]) + __expf(acc[mt][1]);
                rsm[mt][1] += __expf(acc[mt][2]) + __expf(acc[mt][3]);
            }
        }
        __syncthreads();
        if (ch + 2 < 32) loadK(ch + 2, buf);
        else             cp_commit();
    }

#pragma unroll
    for (int mt = 0; mt < 4; mt++)
#pragma unroll
        for (int h = 0; h < 2; h++) {
            float vm = rmx[mt][h], vs = rsm[mt][h];
            vm = fmaxf(vm, __shfl_xor_sync(0xffffffffu, vm, 1));
            vm = fmaxf(vm, __shfl_xor_sync(0xffffffffu, vm, 2));
            vs += __shfl_xor_sync(0xffffffffu, vs, 1);
            vs += __shfl_xor_sync(0xffffffffu, vs, 2);
            if (tig == 0) {
                int row = warpM * 64 + mt * 16 + grp + h * 8;
                RedM[row][warpN] = vm;
                RedS[row][warpN] = vs;
            }
        }
    __syncthreads();
    if (t < 128) {
        float vm = fmaxf(fmaxf(RedM[t][0], RedM[t][1]), fmaxf(RedM[t][2], RedM[t][3]));
        float vs = RedS[t][0] + RedS[t][1] + RedS[t][2] + RedS[t][3];
        g_M[(long)b * NP + n0 + t]      = vm;
        g_invsum[(long)b * NP + n0 + t] = __expf(vm) / vs;
    }
}

// ---------------- fused attention: out1 = Vp @ softmax (P never in gmem) ----------------
// CTA: 128 c-rows x 128 m-cols. Loop 8 n-chunks of 128: E = Qt@K (MMA), exp -> P smem,
// acc += Vp @ P (MMA). K tile loaded once per CTA.
#define KTS 136
#define QS2 40
#define VS  136
#define PS  136
#define OFF_K   0
#define OFF_Q   8704            // 2 x 10240
#define OFF_V   29184           // 34816
#define OFF_P   64000           // 34816
#define OFF_M   98816           // 2 x 512
#define ATTN_SMEM 99840

__global__ __launch_bounds__(256)
void attn_kernel()
{
    extern __shared__ char dsm[];
    uint32_t s0 = (uint32_t)__cvta_generic_to_shared(dsm);
    uint32_t sK = s0 + OFF_K;
    uint32_t sV = s0 + OFF_V;
    uint32_t sP = s0 + OFF_P;

    int b  = blockIdx.z;
    int c0 = blockIdx.y * 128;
    int m0 = blockIdx.x * 128;

    const __half* Qb  = g_Qt  + (long)b * NP * CS;
    const __half* Kb  = g_Yh  + ((long)b * YM + CS) * HW + m0;
    const __half* Vpb = g_Vph + ((long)b * CC + c0) * NP;
    const float*  Mb  = g_M   + (long)b * NP;

    int t = threadIdx.x;
    int lane = t & 31;
    int warp = t >> 5;
    int warpM = warp >> 2, warpN = warp & 3;
    int grp = lane >> 2, tig = lane & 3;

    auto loadK = [&]() {
#pragma unroll
        for (int i = 0; i < 2; i++) {
            int idx = t + 256 * i;
            int r = idx >> 4, cc = (idx & 15) * 8;
            cp16s(sK + (r * KTS + cc) * 2, Kb + (long)r * HW + cc);
        }
    };
    auto loadQM = [&](int ch, int buf) {
        uint32_t q = s0 + OFF_Q + buf * 10240;
#pragma unroll
        for (int i = 0; i < 2; i++) {
            int idx = t + 256 * i;
            int r = idx >> 2, cc = (idx & 3) * 8;
            cp16s(q + (r * QS2 + cc) * 2, Qb + (long)(ch * 128 + r) * CS + cc);
        }
        if (t < 32) cp16s(s0 + OFF_M + buf * 512 + t * 16, Mb + ch * 128 + t * 4);
    };
    auto loadV = [&](int ch) {
#pragma unroll
        for (int i = 0; i < 8; i++) {
            int idx = t + 256 * i;
            int r = idx >> 4, cc = (idx & 15) * 8;
            cp16s(sV + (r * VS + cc) * 2, Vpb + (long)r * NP + ch * 128 + cc);
        }
    };

    loadK(); loadQM(0, 0); loadV(0); cp_commit();
    loadQM(1, 1); cp_commit();

    float acc[4][4][4];
#pragma unroll
    for (int i = 0; i < 4; i++)
#pragma unroll
        for (int j = 0; j < 4; j++)
#pragma unroll
            for (int f = 0; f < 4; f++) acc[i][j][f] = 0.f;

    uint32_t bLaneK = (uint32_t)(((lane & 15) * KTS + warpN * 32) * 2);
    uint32_t aLaneV = (uint32_t)(((lane & 15) * VS + (lane >> 4) * 8) * 2);
    uint32_t bLaneP = (uint32_t)(((lane & 15) * PS + warpN * 32) * 2);

    for (int ch = 0; ch < 8; ch++) {
        int buf = ch & 1;
        cp_wait<1>();
        __syncthreads();

        // phase 1: E = Q @ K, exp(E - M) -> P smem
        {
            uint32_t q = s0 + OFF_Q + buf * 10240;
            const float* MsF = (const float*)(dsm + OFF_M + buf * 512);
            uint32_t aBase = q + (uint32_t)(((warpM * 64 + (lane & 15)) * QS2 + (lane >> 4) * 8) * 2);
            uint32_t af[4][4], af2[4][4];
#pragma unroll
            for (int mt = 0; mt < 4; mt++) {
                ldsm_x4(af[mt][0],  af[mt][1],  af[mt][2],  af[mt][3],
                        aBase + (uint32_t)((mt * 16 * QS2) * 2));
                ldsm_x4(af2[mt][0], af2[mt][1], af2[mt][2], af2[mt][3],
                        aBase + (uint32_t)((mt * 16 * QS2 + 16) * 2));
            }
            uint32_t bBase = sK + bLaneK;
#pragma unroll
            for (int nt = 0; nt < 4; nt++) {
                float e[4][4];
#pragma unroll
                for (int mt = 0; mt < 4; mt++)
#pragma unroll
                    for (int f = 0; f < 4; f++) e[mt][f] = 0.f;
                uint32_t bf0[2], bf1[2];
                ldsm_x2_t(bf0[0], bf0[1], bBase + (uint32_t)((nt * 8) * 2));
                ldsm_x2_t(bf1[0], bf1[1], bBase + (uint32_t)((16 * KTS + nt * 8) * 2));
#pragma unroll
                for (int mt = 0; mt < 4; mt++) {
                    mma_f16(e[mt][0], e[mt][1], e[mt][2], e[mt][3],
                            af[mt][0],  af[mt][1],  af[mt][2],  af[mt][3],  bf0[0], bf0[1]);
                    mma_f16(e[mt][0], e[mt][1], e[mt][2], e[mt][3],
                            af2[mt][0], af2[mt][1], af2[mt][2], af2[mt][3], bf1[0], bf1[1]);
                }
#pragma unroll
                for (int mt = 0; mt < 4; mt++) {
                    int r0 = warpM * 64 + mt * 16 + grp;
                    int r1 = r0 + 8;
                    float m0f = MsF[r0], m1f = MsF[r1];
                    float p0 = __expf(e[mt][0] - m0f);
                    float p1 = __expf(e[mt][1] - m0f);
                    float p2 = __expf(e[mt][2] - m1f);
                    float p3 = __expf(e[mt][3] - m1f);
                    int col = warpN * 32 + nt * 8 + 2 * tig;
                    __half* Pp0 = (__half*)(dsm + OFF_P) + r0 * PS + col;
                    __half* Pp1 = (__half*)(dsm + OFF_P) + r1 * PS + col;
                    *(__half2*)Pp0 = __floats2half2_rn(p0, p1);
                    *(__half2*)Pp1 = __floats2half2_rn(p2, p3);
                }
            }
        }
        __syncthreads();       // P complete, Q[buf] free
        cp_wait<0>();          // Vp[ch] (and Q[ch+1]) resident
        __syncthreads();

        // phase 2: acc += Vp @ P
        {
            uint32_t aBase = sV + (uint32_t)((warpM * 64) * VS * 2) + aLaneV;
            uint32_t bBase = sP + bLaneP;
#pragma unroll
            for (int kb = 0; kb < 128; kb += 16) {
                uint32_t af[4][4], bf[4][2];
#pragma unroll
                for (int mt = 0; mt < 4; mt++)
                    ldsm_x4(af[mt][0], af[mt][1], af[mt][2], af[mt][3],
                            aBase + (uint32_t)((mt * 16 * VS + kb) * 2));
#pragma unroll
                for (int nt = 0; nt < 4; nt++)
                    ldsm_x2_t(bf[nt][0], bf[nt][1],
                              bBase + (uint32_t)((kb * PS + nt * 8) * 2));
#pragma unroll
                for (int mt = 0; mt < 4; mt++)
#pragma unroll
                    for (int nt = 0; nt < 4; nt++)
                        mma_f16(acc[mt][nt][0], acc[mt][nt][1], acc[mt][nt][2], acc[mt][nt][3],
                                af[mt][0], af[mt][1], af[mt][2], af[mt][3],
                                bf[nt][0], bf[nt][1]);
            }
        }
        __syncthreads();       // Vp, P consumed

        if (ch + 1 < 8) {
            loadV(ch + 1);
            if (ch + 2 < 8) loadQM(ch + 2, buf);
            cp_commit();
        }
    }

    // epilogue -> out1h fp16
    __half* Ob = g_out1h + (long)b * CC * HW;
#pragma unroll
    for (int mt = 0; mt < 4; mt++) {
        int r0 = c0 + warpM * 64 + mt * 16 + grp;
        int r1 = r0 + 8;
#pragma unroll
        for (int nt = 0; nt < 4; nt++) {
            int col = m0 + warpN * 32 + nt * 8 + 2 * tig;
            *(__half2*)(Ob + (long)r0 * HW + col) = __floats2half2_rn(acc[mt][nt][0], acc[mt][nt][1]);
            *(__half2*)(Ob + (long)r1 * HW + col) = __floats2half2_rn(acc[mt][nt][2], acc[mt][nt][3]);
        }
    }
}

// ---------------- launch ----------------
extern "C" void kernel_launch(void* const* d_in, const int* in_sizes, int n_in,
                              void* d_out, int out_size)
{
    const float* x     = (const float*)d_in[0];
    const float* wq    = (const float*)d_in[1];
    const float* bq    = (const float*)d_in[2];
    const float* wk    = (const float*)d_in[3];
    const float* bk    = (const float*)d_in[4];
    const float* wv    = (const float*)d_in[5];
    const float* bv    = (const float*)d_in[6];
    const float* wo    = (const float*)d_in[7];
    const float* bo    = (const float*)d_in[8];
    const float* gamma = (const float*)d_in[9];
    float* out = (float*)d_out;

    __half *pWh, *pWoh, *pXh, *pYh, *pOut1h;
    float *pBias;
    cudaGetSymbolAddress((void**)&pWh,    g_Wh);
    cudaGetSymbolAddress((void**)&pBias,  g_bias);
    cudaGetSymbolAddress((void**)&pWoh,   g_Woh);
    cudaGetSymbolAddress((void**)&pXh,    g_Xh);
    cudaGetSymbolAddress((void**)&pYh,    g_Yh);
    cudaGetSymbolAddress((void**)&pOut1h, g_out1h);

    cudaFuncSetAttribute(hgemm<true,  false, true >, cudaFuncAttributeMaxDynamicSharedMemorySize, H_SMEM);
    cudaFuncSetAttribute(hgemm<true,  true,  false>, cudaFuncAttributeMaxDynamicSharedMemorySize, H_SMEM);
    cudaFuncSetAttribute(attn_kernel, cudaFuncAttributeMaxDynamicSharedMemorySize, ATTN_SMEM);

    // 1. pack weights; convert x
    pack_kernel<<<(YM * CC + 255) / 256, 256>>>(wq, bq, wk, bk, wv, bv, wo);
    {
        long total8 = (long)BB * CC * HW / 8;
        cvtx_kernel<<<(int)((total8 + 255) / 256), 256>>>(x);
    }

    // 2. QKV conv -> Yh fp16
    {
        dim3 grid(HW / 128, YM / 128, BB);
        hgemm<true, false, true><<<grid, 256, H_SMEM>>>(
            YM, HW, CC,
            pWh, 0L,
            pXh, (long)CC * HW,
            pYh, (long)YM * HW,
            pBias, nullptr, 0L, nullptr);
    }

    // 3. pool Q (transposed fp16)
    {
        long total = (long)BB * CS * NP;
        poolQ_kernel<<<(int)((total + 255) / 256), 256>>>();
    }

    // 4. rowmax + sum(exp(E)) in one pass -> M, invsum
    {
        dim3 grid(NP / 128, BB);
        maxsumE_kernel<<<grid, 256>>>();
    }

    // 5. pool V with invsum folding -> fp16
    {
        long total = (long)BB * CC * NP;
        poolV_kernel<<<(int)((total + 255) / 256), 256>>>();
    }

    // 6. fused attention: out1 = Vp @ softmax (P stays in smem)
    {
        dim3 grid(HW / 128, CC / 128, BB);
        attn_kernel<<<grid, 256, ATTN_SMEM>>>();
    }

    // 7. out = gamma * (Woh @ out1h + bo) + x
    {
        dim3 grid(HW / 128, CC / 128, BB);
        hgemm<true, true, false><<<grid, 256, H_SMEM>>>(
            CC, HW, CC,
            pWoh, 0L,
            pOut1h, (long)CC * HW,
            out, (long)CC * HW,
            bo,
            x, (long)CC * HW,
            gamma);
    }
}